// round 1
// baseline (speedup 1.0000x reference)
#include <cuda_runtime.h>
#include <cuda_bf16.h>
#include <math.h>

// Problem constants
#define B_    4
#define T_    2048
#define C_    2048
#define NH_   16
#define NKV_  8
#define HD_   128
#define M_    (B_*T_)          // 8192
#define KVD_  (NKV_*HD_)       // 1024

// ---------------- scratch (static device allocations are allowed) ----------
__device__ float g_q[(size_t)M_ * C_];     // 64MB  Q after proj (B,T,H,hd)
__device__ float g_k[(size_t)M_ * KVD_];   // 32MB  K after proj (B,T,KVH,hd)
__device__ float g_v[(size_t)M_ * KVD_];   // 32MB
__device__ float g_o[(size_t)M_ * C_];     // 64MB  attention out (B,T,H,hd)

// ---------------- generic GEMM: C[M,N] = A[M,K] * B[N,K]^T ------------------
#define GBM 128
#define GBN 128
#define GBK 16

__global__ void __launch_bounds__(256) gemm_abt(const float* __restrict__ A,
                                                const float* __restrict__ Bm,
                                                float* __restrict__ Cm,
                                                int M, int N, int K) {
    __shared__ float As[GBK][GBM];
    __shared__ float Bs[GBK][GBN];

    const int tid = threadIdx.x;
    const int tx = tid & 15;        // 0..15 -> N
    const int ty = tid >> 4;        // 0..15 -> M
    const int bx = blockIdx.x;      // N tile
    const int by = blockIdx.y;      // M tile

    const float* Ablk = A + (size_t)by * GBM * K;
    const float* Bblk = Bm + (size_t)bx * GBN * K;

    float acc[8][8];
#pragma unroll
    for (int i = 0; i < 8; i++)
#pragma unroll
        for (int j = 0; j < 8; j++) acc[i][j] = 0.f;

    for (int k0 = 0; k0 < K; k0 += GBK) {
        // Stage A and B tiles: 128 rows x 16 cols each = 512 float4 per tile.
        // l = i*256 + tid : r = l>>2 (row), c = (l&3)*4 (col of 4)
#pragma unroll
        for (int i = 0; i < 2; i++) {
            int l = i * 256 + tid;
            int r = l >> 2;
            int c = (l & 3) * 4;
            float4 va = *(const float4*)(Ablk + (size_t)r * K + k0 + c);
            As[c + 0][r] = va.x; As[c + 1][r] = va.y;
            As[c + 2][r] = va.z; As[c + 3][r] = va.w;
            float4 vb = *(const float4*)(Bblk + (size_t)r * K + k0 + c);
            Bs[c + 0][r] = vb.x; Bs[c + 1][r] = vb.y;
            Bs[c + 2][r] = vb.z; Bs[c + 3][r] = vb.w;
        }
        __syncthreads();

#pragma unroll
        for (int kk = 0; kk < GBK; kk++) {
            float4 a0 = *(const float4*)(&As[kk][ty * 8]);
            float4 a1 = *(const float4*)(&As[kk][ty * 8 + 4]);
            float4 b0 = *(const float4*)(&Bs[kk][tx * 8]);
            float4 b1 = *(const float4*)(&Bs[kk][tx * 8 + 4]);
            float a[8] = {a0.x, a0.y, a0.z, a0.w, a1.x, a1.y, a1.z, a1.w};
            float b[8] = {b0.x, b0.y, b0.z, b0.w, b1.x, b1.y, b1.z, b1.w};
#pragma unroll
            for (int i = 0; i < 8; i++)
#pragma unroll
                for (int j = 0; j < 8; j++)
                    acc[i][j] = fmaf(a[i], b[j], acc[i][j]);
        }
        __syncthreads();
    }

    const int row0 = by * GBM + ty * 8;
    const int col0 = bx * GBN + tx * 8;
#pragma unroll
    for (int i = 0; i < 8; i++) {
        float4 v0 = make_float4(acc[i][0], acc[i][1], acc[i][2], acc[i][3]);
        float4 v1 = make_float4(acc[i][4], acc[i][5], acc[i][6], acc[i][7]);
        *(float4*)(Cm + (size_t)(row0 + i) * N + col0)     = v0;
        *(float4*)(Cm + (size_t)(row0 + i) * N + col0 + 4) = v1;
    }
}

// ---------------- RoPE (in place, layout (B*T, NHd, 128)) -------------------
__global__ void rope_kernel(float* __restrict__ x, int nheads, int total_pairs) {
    int idx = blockIdx.x * blockDim.x + threadIdx.x;
    if (idx >= total_pairs) return;
    int d   = idx & 63;
    int tmp = idx >> 6;
    int h   = tmp % nheads;
    int bt  = tmp / nheads;
    int t   = bt & (T_ - 1);          // T_ = 2048, power of two

    float* base = x + ((size_t)bt * nheads + h) * HD_;
    float x1 = base[d];
    float x2 = base[d + 64];

    int i1 = d >> 1;                  // freq index for lower element
    // inv_freq[i] = 10000^{-i/64} = exp2(-i * log2(10000)/64)
    const float L2C = 0.20762050593046f; // log2(10000)/64
    float inv1 = exp2f(-(float)i1 * L2C);
    float inv2 = exp2f(-(float)(i1 + 32) * L2C);
    float a1 = (float)t * inv1;
    float a2 = (float)t * inv2;
    float s1, c1, s2, c2;
    sincosf(a1, &s1, &c1);
    sincosf(a2, &s2, &c2);

    base[d]      = x1 * c1 - x2 * s1;
    base[d + 64] = x2 * c2 + x1 * s2;
}

// ---------------- Flash attention (fp32) ------------------------------------
#define ABM 64
#define ABN 64
#define AST 132           // padded row stride for Q/K/V tiles
#define SST 65            // padded row stride for S tile

// smem floats: 3*64*132 (Q,K,V) + 64*65 (S) + 3*64 (m,l,alpha)
#define ATT_SMEM_FLOATS (3 * ABM * AST + ABM * SST + 3 * ABM)
#define ATT_SMEM_BYTES  (ATT_SMEM_FLOATS * 4)

__global__ void __launch_bounds__(256, 1) attn_kernel(const float* __restrict__ Q,
                                                      const float* __restrict__ Kx,
                                                      const float* __restrict__ Vx,
                                                      float* __restrict__ O) {
    const int qt  = (int)gridDim.x - 1 - (int)blockIdx.x; // big tiles first
    const int h   = blockIdx.y;
    const int b   = blockIdx.z;
    const int kvh = h >> 1;

    extern __shared__ float sm[];
    float* Qs = sm;
    float* Ks = Qs + ABM * AST;
    float* Vs = Ks + ABN * AST;
    float* Ss = Vs + ABN * AST;
    float* Ms = Ss + ABM * SST;
    float* Ls = Ms + ABM;
    float* Al = Ls + ABM;

    const int tid = threadIdx.x;
    const int tx = tid & 15;
    const int ty = tid >> 4;
    const int r0  = ty * 4;   // S/O row base
    const int cS0 = tx * 4;   // S col base
    const int cO0 = tx * 8;   // O col base

    const int q0 = qt * ABM;

    // load Q tile
    for (int l = tid; l < ABM * 32; l += 256) {
        int r = l >> 5;
        int c = (l & 31) * 4;
        float4 v = *(const float4*)(Q + ((size_t)((b * T_ + q0 + r) * NH_ + h)) * HD_ + c);
        *(float4*)(Qs + r * AST + c) = v;
    }
    if (tid < ABM) { Ms[tid] = -1e30f; Ls[tid] = 0.f; }

    float o[4][8];
#pragma unroll
    for (int i = 0; i < 4; i++)
#pragma unroll
        for (int c = 0; c < 8; c++) o[i][c] = 0.f;

    __syncthreads();

    const float scale = 0.08838834764831845f; // 1/sqrt(128)

    for (int jt = 0; jt <= qt; jt++) {
        // load K,V tiles
        for (int l = tid; l < ABN * 32; l += 256) {
            int r = l >> 5;
            int c = (l & 31) * 4;
            size_t base = ((size_t)((b * T_ + jt * ABN + r) * NKV_ + kvh)) * HD_ + c;
            *(float4*)(Ks + r * AST + c) = *(const float4*)(Kx + base);
            *(float4*)(Vs + r * AST + c) = *(const float4*)(Vx + base);
        }
        __syncthreads();

        // S = Q K^T (each thread: 4x4)
        float acc[4][4];
#pragma unroll
        for (int i = 0; i < 4; i++)
#pragma unroll
            for (int j = 0; j < 4; j++) acc[i][j] = 0.f;

#pragma unroll 8
        for (int kk = 0; kk < HD_; kk += 4) {
            float4 a[4], bb[4];
#pragma unroll
            for (int i = 0; i < 4; i++)
                a[i] = *(const float4*)(Qs + (r0 + i) * AST + kk);
#pragma unroll
            for (int j = 0; j < 4; j++)
                bb[j] = *(const float4*)(Ks + (cS0 + j) * AST + kk);
#pragma unroll
            for (int i = 0; i < 4; i++)
#pragma unroll
                for (int j = 0; j < 4; j++) {
                    acc[i][j] = fmaf(a[i].x, bb[j].x, acc[i][j]);
                    acc[i][j] = fmaf(a[i].y, bb[j].y, acc[i][j]);
                    acc[i][j] = fmaf(a[i].z, bb[j].z, acc[i][j]);
                    acc[i][j] = fmaf(a[i].w, bb[j].w, acc[i][j]);
                }
        }

        const bool diag = (jt == qt);
#pragma unroll
        for (int i = 0; i < 4; i++)
#pragma unroll
            for (int j = 0; j < 4; j++) {
                float s = acc[i][j] * scale;
                if (diag && (jt * ABN + cS0 + j) > (q0 + r0 + i)) s = -1e30f;
                Ss[(r0 + i) * SST + cS0 + j] = s;
            }
        __syncthreads();

        // online softmax, one thread per row
        if (tid < ABM) {
            int r = tid;
            float mprev = Ms[r];
            float mx = mprev;
#pragma unroll 8
            for (int j = 0; j < ABN; j++) mx = fmaxf(mx, Ss[r * SST + j]);
            float sum = 0.f;
#pragma unroll 8
            for (int j = 0; j < ABN; j++) {
                float p = __expf(Ss[r * SST + j] - mx);
                Ss[r * SST + j] = p;
                sum += p;
            }
            float alpha = __expf(mprev - mx);
            Ms[r] = mx;
            Ls[r] = Ls[r] * alpha + sum;
            Al[r] = alpha;
        }
        __syncthreads();

        // O = alpha*O + P @ V
#pragma unroll
        for (int i = 0; i < 4; i++) {
            float al = Al[r0 + i];
#pragma unroll
            for (int c = 0; c < 8; c++) o[i][c] *= al;
        }
#pragma unroll 4
        for (int j = 0; j < ABN; j++) {
            float4 v0 = *(const float4*)(Vs + j * AST + cO0);
            float4 v1 = *(const float4*)(Vs + j * AST + cO0 + 4);
#pragma unroll
            for (int i = 0; i < 4; i++) {
                float p = Ss[(r0 + i) * SST + j];
                o[i][0] = fmaf(p, v0.x, o[i][0]);
                o[i][1] = fmaf(p, v0.y, o[i][1]);
                o[i][2] = fmaf(p, v0.z, o[i][2]);
                o[i][3] = fmaf(p, v0.w, o[i][3]);
                o[i][4] = fmaf(p, v1.x, o[i][4]);
                o[i][5] = fmaf(p, v1.y, o[i][5]);
                o[i][6] = fmaf(p, v1.z, o[i][6]);
                o[i][7] = fmaf(p, v1.w, o[i][7]);
            }
        }
        __syncthreads();
    }

    // epilogue: divide by l, write out
#pragma unroll
    for (int i = 0; i < 4; i++) {
        float inv = 1.f / Ls[r0 + i];
        float4 v0 = make_float4(o[i][0] * inv, o[i][1] * inv, o[i][2] * inv, o[i][3] * inv);
        float4 v1 = make_float4(o[i][4] * inv, o[i][5] * inv, o[i][6] * inv, o[i][7] * inv);
        float* dst = O + ((size_t)((b * T_ + q0 + r0 + i) * NH_ + h)) * HD_ + cO0;
        *(float4*)(dst)     = v0;
        *(float4*)(dst + 4) = v1;
    }
}

// ---------------- launch ----------------------------------------------------
extern "C" void kernel_launch(void* const* d_in, const int* in_sizes, int n_in,
                              void* d_out, int out_size) {
    const float* x  = (const float*)d_in[0];
    const float* Wq = (const float*)d_in[1];
    const float* Wk = (const float*)d_in[2];
    const float* Wv = (const float*)d_in[3];
    const float* Wo = (const float*)d_in[4];
    float* y = (float*)d_out;

    float *q, *k, *v, *o;
    cudaGetSymbolAddress((void**)&q, g_q);
    cudaGetSymbolAddress((void**)&k, g_k);
    cudaGetSymbolAddress((void**)&v, g_v);
    cudaGetSymbolAddress((void**)&o, g_o);

    cudaFuncSetAttribute(attn_kernel, cudaFuncAttributeMaxDynamicSharedMemorySize,
                         ATT_SMEM_BYTES);

    // QKV projections
    gemm_abt<<<dim3(C_ / GBN,  M_ / GBM), 256>>>(x, Wq, q, M_, C_,  C_);
    gemm_abt<<<dim3(KVD_ / GBN, M_ / GBM), 256>>>(x, Wk, k, M_, KVD_, C_);
    gemm_abt<<<dim3(KVD_ / GBN, M_ / GBM), 256>>>(x, Wv, v, M_, KVD_, C_);

    // RoPE
    {
        int qpairs = M_ * NH_ * 64;
        int kpairs = M_ * NKV_ * 64;
        rope_kernel<<<(qpairs + 255) / 256, 256>>>(q, NH_, qpairs);
        rope_kernel<<<(kpairs + 255) / 256, 256>>>(k, NKV_, kpairs);
    }

    // attention
    attn_kernel<<<dim3(T_ / ABM, NH_, B_), 256, ATT_SMEM_BYTES>>>(q, k, v, o);

    // output projection
    gemm_abt<<<dim3(C_ / GBN, M_ / GBM), 256>>>(o, Wo, y, M_, C_, C_);
}

// round 3
// speedup vs baseline: 2.6380x; 2.6380x over previous
#include <cuda_runtime.h>
#include <cuda_bf16.h>
#include <math.h>
#include <stdint.h>

// Problem constants
#define B_    4
#define T_    2048
#define C_    2048
#define NH_   16
#define NKV_  8
#define HD_   128
#define M_    (B_*T_)          // 8192
#define KVD_  (NKV_*HD_)       // 1024

// ---------------- scratch ----------------------------------------------------
__device__ float g_q[(size_t)M_ * C_];     // 64MB  Q after proj (B,T,H,hd)
__device__ float g_k[(size_t)M_ * KVD_];   // 32MB
__device__ float g_v[(size_t)M_ * KVD_];   // 32MB
__device__ float g_o[(size_t)M_ * C_];     // 64MB  attention out (tf32-rounded)
__device__ float g_xr[(size_t)M_ * C_];    // 64MB  x rounded to tf32
__device__ float g_wqr[(size_t)C_ * C_];   // 16MB
__device__ float g_wkr[(size_t)KVD_ * C_]; // 8MB
__device__ float g_wvr[(size_t)KVD_ * C_]; // 8MB
__device__ float g_wor[(size_t)C_ * C_];   // 16MB

// ---------------- helpers ----------------------------------------------------
__device__ __forceinline__ float to_tf32(float x) {
    uint32_t u;
    asm("cvt.rna.tf32.f32 %0, %1;" : "=r"(u) : "f"(x));
    return __uint_as_float(u);
}

__device__ __forceinline__ void cp_async16(void* smem, const void* gmem) {
    uint32_t sa = (uint32_t)__cvta_generic_to_shared(smem);
    asm volatile("cp.async.cg.shared.global [%0], [%1], 16;\n" :: "r"(sa), "l"(gmem));
}
#define CP_COMMIT() asm volatile("cp.async.commit_group;\n" ::: "memory")
#define CP_WAIT(n)  asm volatile("cp.async.wait_group %0;\n" :: "n"(n) : "memory")

#define MMA_TF32(d, a, b) \
    asm volatile("mma.sync.aligned.m16n8k8.row.col.f32.tf32.tf32.f32 " \
                 "{%0,%1,%2,%3}, {%4,%5,%6,%7}, {%8,%9}, {%0,%1,%2,%3};" \
                 : "+f"(d[0]), "+f"(d[1]), "+f"(d[2]), "+f"(d[3]) \
                 : "r"(a[0]), "r"(a[1]), "r"(a[2]), "r"(a[3]), "r"(b[0]), "r"(b[1]))

// ---------------- tf32 rounding pass -----------------------------------------
__global__ void round_tf32_kernel(const float* __restrict__ in, float* __restrict__ out, int n4) {
    int i = blockIdx.x * blockDim.x + threadIdx.x;
    if (i >= n4) return;
    float4 v = ((const float4*)in)[i];
    v.x = to_tf32(v.x); v.y = to_tf32(v.y);
    v.z = to_tf32(v.z); v.w = to_tf32(v.w);
    ((float4*)out)[i] = v;
}

// ---------------- tf32 tensor-core GEMM: C[M,N] = A[M,K] * B[N,K]^T ----------
// CTA tile 128x128x32, 8 warps (2 m x 4 n), warp tile 64x32 (4x4 m16n8k8).
// Smem: [row][k] layout, stride 36 words (conflict-free fragment loads).
#define TBM 128
#define TBN 128
#define TBK 32
#define TSTR 36
#define GEMM_SMEM_BYTES (2 * (TBM * TSTR + TBN * TSTR) * 4)   // 73728

__global__ void __launch_bounds__(256, 1) gemm_tf32(const float* __restrict__ A,
                                                    const float* __restrict__ Bm,
                                                    float* __restrict__ Cm,
                                                    int M, int N, int K) {
    extern __shared__ float sm[];
    float* As = sm;                          // [2][TBM*TSTR]
    float* Bs = sm + 2 * TBM * TSTR;         // [2][TBN*TSTR]

    const int tid = threadIdx.x;
    const int wid = tid >> 5;
    const int lane = tid & 31;
    const int warp_m = wid >> 2;             // 0..1
    const int warp_n = wid & 3;              // 0..3
    const int g = lane >> 2;                 // 0..7
    const int t = lane & 3;                  // 0..3

    const float* Ag = A + (size_t)blockIdx.y * TBM * K;
    const float* Bg = Bm + (size_t)blockIdx.x * TBN * K;

    float c[4][4][4];
#pragma unroll
    for (int mt = 0; mt < 4; mt++)
#pragma unroll
        for (int nt = 0; nt < 4; nt++)
#pragma unroll
            for (int r = 0; r < 4; r++) c[mt][nt][r] = 0.f;

    // tile loader: 4 float4 per thread for A, 4 for B
    auto load_tile = [&](int it, int buf) {
        int k0 = it * TBK;
        float* as = As + buf * TBM * TSTR;
        float* bs = Bs + buf * TBN * TSTR;
#pragma unroll
        for (int i = 0; i < 4; i++) {
            int v = tid + i * 256;
            int r = v >> 3;
            int c4 = (v & 7) * 4;
            cp_async16(as + r * TSTR + c4, Ag + (size_t)r * K + k0 + c4);
            cp_async16(bs + r * TSTR + c4, Bg + (size_t)r * K + k0 + c4);
        }
    };

    const int NIT = K / TBK;
    load_tile(0, 0);
    CP_COMMIT();

    for (int it = 0; it < NIT; ++it) {
        int cur = it & 1;
        if (it + 1 < NIT) {
            load_tile(it + 1, cur ^ 1);
            CP_COMMIT();
            CP_WAIT(1);
        } else {
            CP_WAIT(0);
        }
        __syncthreads();

        const uint32_t* as = (const uint32_t*)(As + cur * TBM * TSTR);
        const uint32_t* bs = (const uint32_t*)(Bs + cur * TBN * TSTR);

#pragma unroll
        for (int kk = 0; kk < TBK; kk += 8) {
            uint32_t af[4][4], bf[4][2];
#pragma unroll
            for (int mt = 0; mt < 4; mt++) {
                int row = warp_m * 64 + mt * 16 + g;
                af[mt][0] = as[row * TSTR + kk + t];
                af[mt][1] = as[(row + 8) * TSTR + kk + t];
                af[mt][2] = as[row * TSTR + kk + t + 4];
                af[mt][3] = as[(row + 8) * TSTR + kk + t + 4];
            }
#pragma unroll
            for (int nt = 0; nt < 4; nt++) {
                int col = warp_n * 32 + nt * 8 + g;
                bf[nt][0] = bs[col * TSTR + kk + t];
                bf[nt][1] = bs[col * TSTR + kk + t + 4];
            }
#pragma unroll
            for (int mt = 0; mt < 4; mt++)
#pragma unroll
                for (int nt = 0; nt < 4; nt++)
                    MMA_TF32(c[mt][nt], af[mt], bf[nt]);
        }
        __syncthreads();
    }

    // epilogue
    const int row_base = blockIdx.y * TBM + warp_m * 64;
    const int col_base = blockIdx.x * TBN + warp_n * 32;
#pragma unroll
    for (int mt = 0; mt < 4; mt++) {
#pragma unroll
        for (int nt = 0; nt < 4; nt++) {
            int row = row_base + mt * 16 + g;
            int col = col_base + nt * 8 + 2 * t;
            *(float2*)(Cm + (size_t)row * N + col)       = make_float2(c[mt][nt][0], c[mt][nt][1]);
            *(float2*)(Cm + (size_t)(row + 8) * N + col) = make_float2(c[mt][nt][2], c[mt][nt][3]);
        }
    }
}

// ---------------- RoPE (in place, layout (B*T, NHd, 128)) --------------------
__global__ void rope_kernel(float* __restrict__ x, int nheads, int total_pairs) {
    int idx = blockIdx.x * blockDim.x + threadIdx.x;
    if (idx >= total_pairs) return;
    int d   = idx & 63;
    int tmp = idx >> 6;
    int h   = tmp % nheads;
    int bt  = tmp / nheads;
    int t   = bt & (T_ - 1);

    float* base = x + ((size_t)bt * nheads + h) * HD_;
    float x1 = base[d];
    float x2 = base[d + 64];

    int i1 = d >> 1;
    const float L2C = 0.20762050593046f; // log2(10000)/64
    float inv1 = exp2f(-(float)i1 * L2C);
    float inv2 = exp2f(-(float)(i1 + 32) * L2C);
    float a1 = (float)t * inv1;
    float a2 = (float)t * inv2;
    float s1, c1, s2, c2;
    sincosf(a1, &s1, &c1);
    sincosf(a2, &s2, &c2);

    base[d]      = x1 * c1 - x2 * s1;
    base[d + 64] = x2 * c2 + x1 * s2;
}

// ---------------- Flash attention (fp32) -------------------------------------
#define ABM 64
#define ABN 64
#define AST 132
#define SST 65
#define ATT_SMEM_FLOATS (3 * ABM * AST + ABM * SST + 3 * ABM)
#define ATT_SMEM_BYTES  (ATT_SMEM_FLOATS * 4)

__global__ void __launch_bounds__(256, 1) attn_kernel(const float* __restrict__ Q,
                                                      const float* __restrict__ Kx,
                                                      const float* __restrict__ Vx,
                                                      float* __restrict__ O) {
    const int qt  = (int)gridDim.x - 1 - (int)blockIdx.x;
    const int h   = blockIdx.y;
    const int b   = blockIdx.z;
    const int kvh = h >> 1;

    extern __shared__ float sm[];
    float* Qs = sm;
    float* Ks = Qs + ABM * AST;
    float* Vs = Ks + ABN * AST;
    float* Ss = Vs + ABN * AST;
    float* Ms = Ss + ABM * SST;
    float* Ls = Ms + ABM;
    float* Al = Ls + ABM;

    const int tid = threadIdx.x;
    const int tx = tid & 15;
    const int ty = tid >> 4;
    const int r0  = ty * 4;
    const int cS0 = tx * 4;
    const int cO0 = tx * 8;

    const int q0 = qt * ABM;

    for (int l = tid; l < ABM * 32; l += 256) {
        int r = l >> 5;
        int c = (l & 31) * 4;
        float4 v = *(const float4*)(Q + ((size_t)((b * T_ + q0 + r) * NH_ + h)) * HD_ + c);
        *(float4*)(Qs + r * AST + c) = v;
    }
    if (tid < ABM) { Ms[tid] = -1e30f; Ls[tid] = 0.f; }

    float o[4][8];
#pragma unroll
    for (int i = 0; i < 4; i++)
#pragma unroll
        for (int c = 0; c < 8; c++) o[i][c] = 0.f;

    __syncthreads();

    const float scale = 0.08838834764831845f;

    for (int jt = 0; jt <= qt; jt++) {
        for (int l = tid; l < ABN * 32; l += 256) {
            int r = l >> 5;
            int c = (l & 31) * 4;
            size_t base = ((size_t)((b * T_ + jt * ABN + r) * NKV_ + kvh)) * HD_ + c;
            *(float4*)(Ks + r * AST + c) = *(const float4*)(Kx + base);
            *(float4*)(Vs + r * AST + c) = *(const float4*)(Vx + base);
        }
        __syncthreads();

        float acc[4][4];
#pragma unroll
        for (int i = 0; i < 4; i++)
#pragma unroll
            for (int j = 0; j < 4; j++) acc[i][j] = 0.f;

#pragma unroll 8
        for (int kk = 0; kk < HD_; kk += 4) {
            float4 a[4], bb[4];
#pragma unroll
            for (int i = 0; i < 4; i++)
                a[i] = *(const float4*)(Qs + (r0 + i) * AST + kk);
#pragma unroll
            for (int j = 0; j < 4; j++)
                bb[j] = *(const float4*)(Ks + (cS0 + j) * AST + kk);
#pragma unroll
            for (int i = 0; i < 4; i++)
#pragma unroll
                for (int j = 0; j < 4; j++) {
                    acc[i][j] = fmaf(a[i].x, bb[j].x, acc[i][j]);
                    acc[i][j] = fmaf(a[i].y, bb[j].y, acc[i][j]);
                    acc[i][j] = fmaf(a[i].z, bb[j].z, acc[i][j]);
                    acc[i][j] = fmaf(a[i].w, bb[j].w, acc[i][j]);
                }
        }

        const bool diag = (jt == qt);
#pragma unroll
        for (int i = 0; i < 4; i++)
#pragma unroll
            for (int j = 0; j < 4; j++) {
                float s = acc[i][j] * scale;
                if (diag && (jt * ABN + cS0 + j) > (q0 + r0 + i)) s = -1e30f;
                Ss[(r0 + i) * SST + cS0 + j] = s;
            }
        __syncthreads();

        if (tid < ABM) {
            int r = tid;
            float mprev = Ms[r];
            float mx = mprev;
#pragma unroll 8
            for (int j = 0; j < ABN; j++) mx = fmaxf(mx, Ss[r * SST + j]);
            float sum = 0.f;
#pragma unroll 8
            for (int j = 0; j < ABN; j++) {
                float p = __expf(Ss[r * SST + j] - mx);
                Ss[r * SST + j] = p;
                sum += p;
            }
            float alpha = __expf(mprev - mx);
            Ms[r] = mx;
            Ls[r] = Ls[r] * alpha + sum;
            Al[r] = alpha;
        }
        __syncthreads();

#pragma unroll
        for (int i = 0; i < 4; i++) {
            float al = Al[r0 + i];
#pragma unroll
            for (int c = 0; c < 8; c++) o[i][c] *= al;
        }
#pragma unroll 4
        for (int j = 0; j < ABN; j++) {
            float4 v0 = *(const float4*)(Vs + j * AST + cO0);
            float4 v1 = *(const float4*)(Vs + j * AST + cO0 + 4);
#pragma unroll
            for (int i = 0; i < 4; i++) {
                float p = Ss[(r0 + i) * SST + j];
                o[i][0] = fmaf(p, v0.x, o[i][0]);
                o[i][1] = fmaf(p, v0.y, o[i][1]);
                o[i][2] = fmaf(p, v0.z, o[i][2]);
                o[i][3] = fmaf(p, v0.w, o[i][3]);
                o[i][4] = fmaf(p, v1.x, o[i][4]);
                o[i][5] = fmaf(p, v1.y, o[i][5]);
                o[i][6] = fmaf(p, v1.z, o[i][6]);
                o[i][7] = fmaf(p, v1.w, o[i][7]);
            }
        }
        __syncthreads();
    }

    // epilogue: divide by l, round to tf32 (feeds final tensor-core GEMM), store
#pragma unroll
    for (int i = 0; i < 4; i++) {
        float inv = 1.f / Ls[r0 + i];
        float4 v0, v1;
        v0.x = to_tf32(o[i][0] * inv); v0.y = to_tf32(o[i][1] * inv);
        v0.z = to_tf32(o[i][2] * inv); v0.w = to_tf32(o[i][3] * inv);
        v1.x = to_tf32(o[i][4] * inv); v1.y = to_tf32(o[i][5] * inv);
        v1.z = to_tf32(o[i][6] * inv); v1.w = to_tf32(o[i][7] * inv);
        float* dst = O + ((size_t)((b * T_ + q0 + r0 + i) * NH_ + h)) * HD_ + cO0;
        *(float4*)(dst)     = v0;
        *(float4*)(dst + 4) = v1;
    }
}

// ---------------- launch ------------------------------------------------------
extern "C" void kernel_launch(void* const* d_in, const int* in_sizes, int n_in,
                              void* d_out, int out_size) {
    const float* x  = (const float*)d_in[0];
    const float* Wq = (const float*)d_in[1];
    const float* Wk = (const float*)d_in[2];
    const float* Wv = (const float*)d_in[3];
    const float* Wo = (const float*)d_in[4];
    float* y = (float*)d_out;

    float *q, *k, *v, *o, *xr, *wqr, *wkr, *wvr, *wor;
    cudaGetSymbolAddress((void**)&q,  g_q);
    cudaGetSymbolAddress((void**)&k,  g_k);
    cudaGetSymbolAddress((void**)&v,  g_v);
    cudaGetSymbolAddress((void**)&o,  g_o);
    cudaGetSymbolAddress((void**)&xr, g_xr);
    cudaGetSymbolAddress((void**)&wqr, g_wqr);
    cudaGetSymbolAddress((void**)&wkr, g_wkr);
    cudaGetSymbolAddress((void**)&wvr, g_wvr);
    cudaGetSymbolAddress((void**)&wor, g_wor);

    cudaFuncSetAttribute(attn_kernel, cudaFuncAttributeMaxDynamicSharedMemorySize,
                         ATT_SMEM_BYTES);
    cudaFuncSetAttribute(gemm_tf32, cudaFuncAttributeMaxDynamicSharedMemorySize,
                         GEMM_SMEM_BYTES);

    // tf32 pre-rounding (makes in-MMA truncation exact == RNA rounding)
    {
        int n4x = M_ * C_ / 4;
        int n4q = C_ * C_ / 4;
        int n4k = KVD_ * C_ / 4;
        round_tf32_kernel<<<(n4x + 255) / 256, 256>>>(x,  xr,  n4x);
        round_tf32_kernel<<<(n4q + 255) / 256, 256>>>(Wq, wqr, n4q);
        round_tf32_kernel<<<(n4k + 255) / 256, 256>>>(Wk, wkr, n4k);
        round_tf32_kernel<<<(n4k + 255) / 256, 256>>>(Wv, wvr, n4k);
        round_tf32_kernel<<<(n4q + 255) / 256, 256>>>(Wo, wor, n4q);
    }

    // QKV projections (tensor cores, tf32)
    gemm_tf32<<<dim3(C_ / TBN,  M_ / TBM), 256, GEMM_SMEM_BYTES>>>(xr, wqr, q, M_, C_,  C_);
    gemm_tf32<<<dim3(KVD_ / TBN, M_ / TBM), 256, GEMM_SMEM_BYTES>>>(xr, wkr, k, M_, KVD_, C_);
    gemm_tf32<<<dim3(KVD_ / TBN, M_ / TBM), 256, GEMM_SMEM_BYTES>>>(xr, wvr, v, M_, KVD_, C_);

    // RoPE
    {
        int qpairs = M_ * NH_ * 64;
        int kpairs = M_ * NKV_ * 64;
        rope_kernel<<<(qpairs + 255) / 256, 256>>>(q, NH_, qpairs);
        rope_kernel<<<(kpairs + 255) / 256, 256>>>(k, NKV_, kpairs);
    }

    // attention
    attn_kernel<<<dim3(T_ / ABM, NH_, B_), 256, ATT_SMEM_BYTES>>>(q, k, v, o);

    // output projection (tensor cores, tf32)
    gemm_tf32<<<dim3(C_ / TBN, M_ / TBM), 256, GEMM_SMEM_BYTES>>>(o, wor, y, M_, C_, C_);
}

// round 5
// speedup vs baseline: 6.0953x; 2.3106x over previous
#include <cuda_runtime.h>
#include <cuda_bf16.h>
#include <math.h>
#include <stdint.h>

// Problem constants
#define B_    4
#define T_    2048
#define C_    2048
#define NH_   16
#define NKV_  8
#define HD_   128
#define M_    (B_*T_)          // 8192
#define KVD_  (NKV_*HD_)       // 1024

// ---------------- scratch ----------------------------------------------------
__device__ float g_q[(size_t)M_ * C_];     // Q after proj+rope (B,T,H,hd), tf32-rounded
__device__ float g_k[(size_t)M_ * KVD_];   // K after proj+rope, tf32-rounded
__device__ float g_v[(size_t)M_ * KVD_];   // V after proj (fp32)
__device__ float g_vt[(size_t)B_ * NKV_ * HD_ * T_]; // V transposed (b,kvh,hd,t), tf32
__device__ float g_o[(size_t)M_ * C_];     // attention out (tf32-rounded)
__device__ float g_xr[(size_t)M_ * C_];    // x rounded to tf32
__device__ float g_wqr[(size_t)C_ * C_];
__device__ float g_wkr[(size_t)KVD_ * C_];
__device__ float g_wvr[(size_t)KVD_ * C_];
__device__ float g_wor[(size_t)C_ * C_];

// ---------------- helpers ----------------------------------------------------
__device__ __forceinline__ float to_tf32(float x) {
    uint32_t u;
    asm("cvt.rna.tf32.f32 %0, %1;" : "=r"(u) : "f"(x));
    return __uint_as_float(u);
}

__device__ __forceinline__ void cp_async16(void* smem, const void* gmem) {
    uint32_t sa = (uint32_t)__cvta_generic_to_shared(smem);
    asm volatile("cp.async.cg.shared.global [%0], [%1], 16;\n" :: "r"(sa), "l"(gmem));
}
#define CP_COMMIT() asm volatile("cp.async.commit_group;\n" ::: "memory")
#define CP_WAIT(n)  asm volatile("cp.async.wait_group %0;\n" :: "n"(n) : "memory")

#define MMA_TF32(d, a, b) \
    asm volatile("mma.sync.aligned.m16n8k8.row.col.f32.tf32.tf32.f32 " \
                 "{%0,%1,%2,%3}, {%4,%5,%6,%7}, {%8,%9}, {%0,%1,%2,%3};" \
                 : "+f"(d[0]), "+f"(d[1]), "+f"(d[2]), "+f"(d[3]) \
                 : "r"(a[0]), "r"(a[1]), "r"(a[2]), "r"(a[3]), "r"(b[0]), "r"(b[1]))

// ---------------- tf32 rounding pass -----------------------------------------
__global__ void round_tf32_kernel(const float* __restrict__ in, float* __restrict__ out, int n4) {
    int i = blockIdx.x * blockDim.x + threadIdx.x;
    if (i >= n4) return;
    float4 v = ((const float4*)in)[i];
    v.x = to_tf32(v.x); v.y = to_tf32(v.y);
    v.z = to_tf32(v.z); v.w = to_tf32(v.w);
    ((float4*)out)[i] = v;
}

// ---------------- tf32 tensor-core GEMM: C[M,N] = A[M,K] * B[N,K]^T ----------
#define TBM 128
#define TBN 128
#define TBK 32
#define TSTR 36
#define GEMM_SMEM_BYTES (2 * (TBM * TSTR + TBN * TSTR) * 4)   // 73728

__global__ void __launch_bounds__(256, 1) gemm_tf32(const float* __restrict__ A,
                                                    const float* __restrict__ Bm,
                                                    float* __restrict__ Cm,
                                                    int M, int N, int K) {
    extern __shared__ float sm[];
    float* As = sm;
    float* Bs = sm + 2 * TBM * TSTR;

    const int tid = threadIdx.x;
    const int wid = tid >> 5;
    const int lane = tid & 31;
    const int warp_m = wid >> 2;
    const int warp_n = wid & 3;
    const int g = lane >> 2;
    const int t = lane & 3;

    const float* Ag = A + (size_t)blockIdx.y * TBM * K;
    const float* Bg = Bm + (size_t)blockIdx.x * TBN * K;

    float c[4][4][4];
#pragma unroll
    for (int mt = 0; mt < 4; mt++)
#pragma unroll
        for (int nt = 0; nt < 4; nt++)
#pragma unroll
            for (int r = 0; r < 4; r++) c[mt][nt][r] = 0.f;

    auto load_tile = [&](int it, int buf) {
        int k0 = it * TBK;
        float* as = As + buf * TBM * TSTR;
        float* bs = Bs + buf * TBN * TSTR;
#pragma unroll
        for (int i = 0; i < 4; i++) {
            int v = tid + i * 256;
            int r = v >> 3;
            int c4 = (v & 7) * 4;
            cp_async16(as + r * TSTR + c4, Ag + (size_t)r * K + k0 + c4);
            cp_async16(bs + r * TSTR + c4, Bg + (size_t)r * K + k0 + c4);
        }
    };

    const int NIT = K / TBK;
    load_tile(0, 0);
    CP_COMMIT();

    for (int it = 0; it < NIT; ++it) {
        int cur = it & 1;
        if (it + 1 < NIT) {
            load_tile(it + 1, cur ^ 1);
            CP_COMMIT();
            CP_WAIT(1);
        } else {
            CP_WAIT(0);
        }
        __syncthreads();

        const uint32_t* as = (const uint32_t*)(As + cur * TBM * TSTR);
        const uint32_t* bs = (const uint32_t*)(Bs + cur * TBN * TSTR);

#pragma unroll
        for (int kk = 0; kk < TBK; kk += 8) {
            uint32_t af[4][4], bf[4][2];
#pragma unroll
            for (int mt = 0; mt < 4; mt++) {
                int row = warp_m * 64 + mt * 16 + g;
                af[mt][0] = as[row * TSTR + kk + t];
                af[mt][1] = as[(row + 8) * TSTR + kk + t];
                af[mt][2] = as[row * TSTR + kk + t + 4];
                af[mt][3] = as[(row + 8) * TSTR + kk + t + 4];
            }
#pragma unroll
            for (int nt = 0; nt < 4; nt++) {
                int col = warp_n * 32 + nt * 8 + g;
                bf[nt][0] = bs[col * TSTR + kk + t];
                bf[nt][1] = bs[col * TSTR + kk + t + 4];
            }
#pragma unroll
            for (int mt = 0; mt < 4; mt++)
#pragma unroll
                for (int nt = 0; nt < 4; nt++)
                    MMA_TF32(c[mt][nt], af[mt], bf[nt]);
        }
        __syncthreads();
    }

    const int row_base = blockIdx.y * TBM + warp_m * 64;
    const int col_base = blockIdx.x * TBN + warp_n * 32;
#pragma unroll
    for (int mt = 0; mt < 4; mt++) {
#pragma unroll
        for (int nt = 0; nt < 4; nt++) {
            int row = row_base + mt * 16 + g;
            int col = col_base + nt * 8 + 2 * t;
            *(float2*)(Cm + (size_t)row * N + col)       = make_float2(c[mt][nt][0], c[mt][nt][1]);
            *(float2*)(Cm + (size_t)(row + 8) * N + col) = make_float2(c[mt][nt][2], c[mt][nt][3]);
        }
    }
}

// ---------------- RoPE (in place; outputs tf32-rounded for MMA) --------------
__global__ void rope_kernel(float* __restrict__ x, int nheads, int total_pairs) {
    int idx = blockIdx.x * blockDim.x + threadIdx.x;
    if (idx >= total_pairs) return;
    int d   = idx & 63;
    int tmp = idx >> 6;
    int h   = tmp % nheads;
    int bt  = tmp / nheads;
    int t   = bt & (T_ - 1);

    float* base = x + ((size_t)bt * nheads + h) * HD_;
    float x1 = base[d];
    float x2 = base[d + 64];

    int i1 = d >> 1;
    const float L2C = 0.20762050593046f; // log2(10000)/64
    float inv1 = exp2f(-(float)i1 * L2C);
    float inv2 = exp2f(-(float)(i1 + 32) * L2C);
    float a1 = (float)t * inv1;
    float a2 = (float)t * inv2;
    float s1, c1, s2, c2;
    sincosf(a1, &s1, &c1);
    sincosf(a2, &s2, &c2);

    base[d]      = to_tf32(x1 * c1 - x2 * s1);
    base[d + 64] = to_tf32(x2 * c2 + x1 * s2);
}

// ---------------- V transpose: (b,t,kvh,hd) -> (b,kvh,hd,t), tf32-rounded ----
__global__ void vtrans_kernel(const float* __restrict__ V, float* __restrict__ Vt) {
    __shared__ float tile[32][33];
    const int z = blockIdx.z;
    const int b = z / NKV_;
    const int kvh = z % NKV_;
    const int t0 = blockIdx.x * 32;
    const int h0 = blockIdx.y * 32;

#pragma unroll
    for (int i = 0; i < 4; i++) {
        int tt = t0 + threadIdx.y + i * 8;
        tile[threadIdx.y + i * 8][threadIdx.x] =
            V[((size_t)(b * T_ + tt) * NKV_ + kvh) * HD_ + h0 + threadIdx.x];
    }
    __syncthreads();
#pragma unroll
    for (int i = 0; i < 4; i++) {
        int hd = h0 + threadIdx.y + i * 8;
        int tt = t0 + threadIdx.x;
        Vt[((size_t)(b * NKV_ + kvh) * HD_ + hd) * T_ + tt] =
            to_tf32(tile[threadIdx.x][threadIdx.y + i * 8]);
    }
}

// ---------------- Flash attention (tf32 tensor cores) ------------------------
#define ABM 64
#define ABN 64
#define AQST 132          // Q/K tile row stride (mod 32 == 4 -> conflict-free frags)
#define AVST 68           // Vt tile row stride
#define ASST 68           // S/P tile row stride

// smem floats: Q 64*132 + K 2*64*132 + Vt 2*128*68 + S 64*68 + stats 3*64
#define ATT_SMEM_FLOATS (ABM*AQST + 2*ABN*AQST + 2*HD_*AVST + ABM*ASST + 3*ABM)
#define ATT_SMEM_BYTES  (ATT_SMEM_FLOATS * 4)   // 189184

__global__ void __launch_bounds__(256, 1) attn_kernel(const float* __restrict__ Q,
                                                      const float* __restrict__ Kx,
                                                      const float* __restrict__ Vt,
                                                      float* __restrict__ O) {
    const int qt  = (int)gridDim.x - 1 - (int)blockIdx.x; // big tiles first
    const int h   = blockIdx.y;
    const int b   = blockIdx.z;
    const int kvh = h >> 1;

    extern __shared__ float sm[];
    float* Qs  = sm;                            // [64][132]
    float* Ks  = Qs + ABM * AQST;               // [2][64][132]
    float* Vs  = Ks + 2 * ABN * AQST;           // [2][128][68]
    float* Ss  = Vs + 2 * HD_ * AVST;           // [64][68]
    float* Ms  = Ss + ABM * ASST;
    float* Ls  = Ms + ABM;
    float* Al  = Ls + ABM;

    const int tid  = threadIdx.x;
    const int wid  = tid >> 5;
    const int lane = tid & 31;
    const int warp_m = wid & 3;                 // 0..3 -> 16-row band
    const int warp_n = wid >> 2;                // 0..1
    const int g = lane >> 2;                    // 0..7
    const int t = lane & 3;                     // 0..3
    const int row0  = warp_m * 16;
    const int scol0 = warp_n * 32;              // S cols
    const int ocol0 = warp_n * 64;              // O cols (hd)

    const int q0 = qt * ABM;
    const float* vtb = Vt + (size_t)(b * NKV_ + kvh) * HD_ * T_;

    // preload Q tile (plain loads)
    for (int l = tid; l < ABM * 32; l += 256) {
        int r = l >> 5;
        int c = (l & 31) * 4;
        *(float4*)(Qs + r * AQST + c) =
            *(const float4*)(Q + ((size_t)((b * T_ + q0 + r) * NH_ + h)) * HD_ + c);
    }
    if (tid < ABM) { Ms[tid] = -1e30f; Ls[tid] = 0.f; }

    // K/Vt tile loader via cp.async
    auto load_kv = [&](int jt, int buf) {
        const int j0 = jt * ABN;
        float* ks = Ks + buf * ABN * AQST;
        float* vs = Vs + buf * HD_ * AVST;
#pragma unroll
        for (int i = 0; i < 8; i++) {
            int v = i * 256 + tid;
            int r = v >> 5;                 // 0..63
            int c4 = (v & 31) * 4;          // 0..124
            cp_async16(ks + r * AQST + c4,
                       Kx + ((size_t)((b * T_ + j0 + r) * NKV_ + kvh)) * HD_ + c4);
        }
#pragma unroll
        for (int i = 0; i < 8; i++) {
            int v = i * 256 + tid;
            int r = v >> 4;                 // 0..127 (hd)
            int c4 = (v & 15) * 4;          // 0..60 (seq)
            cp_async16(vs + r * AVST + c4, vtb + (size_t)r * T_ + j0 + c4);
        }
    };

    float o[8][4];
#pragma unroll
    for (int nt = 0; nt < 8; nt++)
#pragma unroll
        for (int r = 0; r < 4; r++) o[nt][r] = 0.f;

    load_kv(0, 0);
    CP_COMMIT();

    const float scale = 0.08838834764831845f; // 1/sqrt(128)

    for (int jt = 0; jt <= qt; jt++) {
        const int cur = jt & 1;
        if (jt < qt) {
            load_kv(jt + 1, cur ^ 1);
            CP_COMMIT();
            CP_WAIT(1);
        } else {
            CP_WAIT(0);
        }
        __syncthreads();

        // ---- S = Q K^T (registers) ----
        const uint32_t* qs = (const uint32_t*)Qs;
        const uint32_t* ks = (const uint32_t*)(Ks + cur * ABN * AQST);
        float s[4][4];
#pragma unroll
        for (int nt = 0; nt < 4; nt++)
#pragma unroll
            for (int r = 0; r < 4; r++) s[nt][r] = 0.f;

#pragma unroll
        for (int kk = 0; kk < HD_; kk += 8) {
            uint32_t af[4], bf[4][2];
            af[0] = qs[(row0 + g) * AQST + kk + t];
            af[1] = qs[(row0 + 8 + g) * AQST + kk + t];
            af[2] = qs[(row0 + g) * AQST + kk + t + 4];
            af[3] = qs[(row0 + 8 + g) * AQST + kk + t + 4];
#pragma unroll
            for (int nt = 0; nt < 4; nt++) {
                int col = scol0 + nt * 8 + g;
                bf[nt][0] = ks[col * AQST + kk + t];
                bf[nt][1] = ks[col * AQST + kk + t + 4];
            }
#pragma unroll
            for (int nt = 0; nt < 4; nt++)
                MMA_TF32(s[nt], af, bf[nt]);
        }

        // ---- scale + causal mask + store to smem ----
        const bool diag = (jt == qt);
#pragma unroll
        for (int nt = 0; nt < 4; nt++) {
            int c0 = scol0 + nt * 8 + 2 * t;
            int rlo = row0 + g, rhi = row0 + 8 + g;
            float v0 = s[nt][0] * scale, v1 = s[nt][1] * scale;
            float v2 = s[nt][2] * scale, v3 = s[nt][3] * scale;
            if (diag) {
                int gc0 = jt * ABN + c0;
                if (gc0     > q0 + rlo) v0 = -1e30f;
                if (gc0 + 1 > q0 + rlo) v1 = -1e30f;
                if (gc0     > q0 + rhi) v2 = -1e30f;
                if (gc0 + 1 > q0 + rhi) v3 = -1e30f;
            }
            *(float2*)(Ss + rlo * ASST + c0) = make_float2(v0, v1);
            *(float2*)(Ss + rhi * ASST + c0) = make_float2(v2, v3);
        }
        __syncthreads();

        // ---- online softmax: 4 threads per row, interleaved columns ----
        {
            int row = tid >> 2;
            int q4 = tid & 3;
            float mprev = Ms[row];
            float mx = -1e30f;
#pragma unroll
            for (int i = 0; i < 16; i++)
                mx = fmaxf(mx, Ss[row * ASST + q4 + 4 * i]);
            mx = fmaxf(mx, __shfl_xor_sync(0xffffffffu, mx, 1));
            mx = fmaxf(mx, __shfl_xor_sync(0xffffffffu, mx, 2));
            mx = fmaxf(mx, mprev);
            float sum = 0.f;
#pragma unroll
            for (int i = 0; i < 16; i++) {
                float p = to_tf32(__expf(Ss[row * ASST + q4 + 4 * i] - mx));
                Ss[row * ASST + q4 + 4 * i] = p;
                sum += p;
            }
            sum += __shfl_xor_sync(0xffffffffu, sum, 1);
            sum += __shfl_xor_sync(0xffffffffu, sum, 2);
            if (q4 == 0) {
                float alpha = __expf(mprev - mx);
                Ms[row] = mx;
                Ls[row] = Ls[row] * alpha + sum;
                Al[row] = alpha;
            }
        }
        __syncthreads();

        // ---- O = alpha*O + P @ V ----
        {
            float al_lo = Al[row0 + g];
            float al_hi = Al[row0 + 8 + g];
#pragma unroll
            for (int nt = 0; nt < 8; nt++) {
                o[nt][0] *= al_lo; o[nt][1] *= al_lo;
                o[nt][2] *= al_hi; o[nt][3] *= al_hi;
            }
            const uint32_t* ss = (const uint32_t*)Ss;
            const uint32_t* vs = (const uint32_t*)(Vs + cur * HD_ * AVST);
#pragma unroll
            for (int kk = 0; kk < ABN; kk += 8) {
                uint32_t af[4], bf[8][2];
                af[0] = ss[(row0 + g) * ASST + kk + t];
                af[1] = ss[(row0 + 8 + g) * ASST + kk + t];
                af[2] = ss[(row0 + g) * ASST + kk + t + 4];
                af[3] = ss[(row0 + 8 + g) * ASST + kk + t + 4];
#pragma unroll
                for (int nt = 0; nt < 8; nt++) {
                    int n = ocol0 + nt * 8 + g;
                    bf[nt][0] = vs[n * AVST + kk + t];
                    bf[nt][1] = vs[n * AVST + kk + t + 4];
                }
#pragma unroll
                for (int nt = 0; nt < 8; nt++)
                    MMA_TF32(o[nt], af, bf[nt]);
            }
        }
        __syncthreads();   // protect K/V buffer reuse + Ss rewrite
    }

    // ---- epilogue: divide by l, round to tf32, store ----
    {
        float inv_lo = 1.f / Ls[row0 + g];
        float inv_hi = 1.f / Ls[row0 + 8 + g];
        float* dlo = O + ((size_t)((b * T_ + q0 + row0 + g) * NH_ + h)) * HD_;
        float* dhi = O + ((size_t)((b * T_ + q0 + row0 + 8 + g) * NH_ + h)) * HD_;
#pragma unroll
        for (int nt = 0; nt < 8; nt++) {
            int col = ocol0 + nt * 8 + 2 * t;
            *(float2*)(dlo + col) = make_float2(to_tf32(o[nt][0] * inv_lo),
                                                to_tf32(o[nt][1] * inv_lo));
            *(float2*)(dhi + col) = make_float2(to_tf32(o[nt][2] * inv_hi),
                                                to_tf32(o[nt][3] * inv_hi));
        }
    }
}

// ---------------- launch ------------------------------------------------------
extern "C" void kernel_launch(void* const* d_in, const int* in_sizes, int n_in,
                              void* d_out, int out_size) {
    const float* x  = (const float*)d_in[0];
    const float* Wq = (const float*)d_in[1];
    const float* Wk = (const float*)d_in[2];
    const float* Wv = (const float*)d_in[3];
    const float* Wo = (const float*)d_in[4];
    float* y = (float*)d_out;

    float *q, *k, *v, *vt, *o, *xr, *wqr, *wkr, *wvr, *wor;
    cudaGetSymbolAddress((void**)&q,  g_q);
    cudaGetSymbolAddress((void**)&k,  g_k);
    cudaGetSymbolAddress((void**)&v,  g_v);
    cudaGetSymbolAddress((void**)&vt, g_vt);
    cudaGetSymbolAddress((void**)&o,  g_o);
    cudaGetSymbolAddress((void**)&xr, g_xr);
    cudaGetSymbolAddress((void**)&wqr, g_wqr);
    cudaGetSymbolAddress((void**)&wkr, g_wkr);
    cudaGetSymbolAddress((void**)&wvr, g_wvr);
    cudaGetSymbolAddress((void**)&wor, g_wor);

    cudaFuncSetAttribute(attn_kernel, cudaFuncAttributeMaxDynamicSharedMemorySize,
                         ATT_SMEM_BYTES);
    cudaFuncSetAttribute(gemm_tf32, cudaFuncAttributeMaxDynamicSharedMemorySize,
                         GEMM_SMEM_BYTES);

    // tf32 pre-rounding
    {
        int n4x = M_ * C_ / 4;
        int n4q = C_ * C_ / 4;
        int n4k = KVD_ * C_ / 4;
        round_tf32_kernel<<<(n4x + 255) / 256, 256>>>(x,  xr,  n4x);
        round_tf32_kernel<<<(n4q + 255) / 256, 256>>>(Wq, wqr, n4q);
        round_tf32_kernel<<<(n4k + 255) / 256, 256>>>(Wk, wkr, n4k);
        round_tf32_kernel<<<(n4k + 255) / 256, 256>>>(Wv, wvr, n4k);
        round_tf32_kernel<<<(n4q + 255) / 256, 256>>>(Wo, wor, n4q);
    }

    // QKV projections (tensor cores, tf32)
    gemm_tf32<<<dim3(C_ / TBN,  M_ / TBM), 256, GEMM_SMEM_BYTES>>>(xr, wqr, q, M_, C_,  C_);
    gemm_tf32<<<dim3(KVD_ / TBN, M_ / TBM), 256, GEMM_SMEM_BYTES>>>(xr, wkr, k, M_, KVD_, C_);
    gemm_tf32<<<dim3(KVD_ / TBN, M_ / TBM), 256, GEMM_SMEM_BYTES>>>(xr, wvr, v, M_, KVD_, C_);

    // RoPE (writes tf32-rounded q,k)
    {
        int qpairs = M_ * NH_ * 64;
        int kpairs = M_ * NKV_ * 64;
        rope_kernel<<<(qpairs + 255) / 256, 256>>>(q, NH_, qpairs);
        rope_kernel<<<(kpairs + 255) / 256, 256>>>(k, NKV_, kpairs);
    }

    // V transpose (b,t,kvh,hd) -> (b,kvh,hd,t), tf32-rounded
    vtrans_kernel<<<dim3(T_ / 32, HD_ / 32, B_ * NKV_), dim3(32, 8)>>>(v, vt);

    // attention (tensor cores)
    attn_kernel<<<dim3(T_ / ABM, NH_, B_), 256, ATT_SMEM_BYTES>>>(q, k, vt, o);

    // output projection (tensor cores, tf32)
    gemm_tf32<<<dim3(C_ / TBN, M_ / TBM), 256, GEMM_SMEM_BYTES>>>(o, wor, y, M_, C_, C_);
}

// round 7
// speedup vs baseline: 7.2216x; 1.1848x over previous
#include <cuda_runtime.h>
#include <cuda_bf16.h>
#include <math.h>
#include <stdint.h>

// Problem constants
#define B_    4
#define T_    2048
#define C_    2048
#define NH_   16
#define NKV_  8
#define HD_   128
#define M_    (B_*T_)          // 8192
#define KVD_  (NKV_*HD_)       // 1024
#define QKVN  (C_ + 2*KVD_)    // 4096 fused projection width

// ---------------- scratch ----------------------------------------------------
__device__ float g_qkv[(size_t)M_ * QKVN];   // 128MB fused QKV output
__device__ float g_vt[(size_t)B_ * NKV_ * HD_ * T_]; // 32MB V transposed, tf32
__device__ float g_o[(size_t)M_ * C_];       // 64MB attention out (tf32-rounded)
__device__ float g_xr[(size_t)M_ * C_];      // 64MB x rounded to tf32
__device__ float g_wqkv[(size_t)QKVN * C_];  // 32MB concat rounded Wq|Wk|Wv
__device__ float g_wor[(size_t)C_ * C_];     // 16MB

// ---------------- helpers ----------------------------------------------------
__device__ __forceinline__ float to_tf32(float x) {
    uint32_t u;
    asm("cvt.rna.tf32.f32 %0, %1;" : "=r"(u) : "f"(x));
    return __uint_as_float(u);
}

__device__ __forceinline__ void cp_async16(void* smem, const void* gmem) {
    uint32_t sa = (uint32_t)__cvta_generic_to_shared(smem);
    asm volatile("cp.async.cg.shared.global [%0], [%1], 16;\n" :: "r"(sa), "l"(gmem));
}
#define CP_COMMIT() asm volatile("cp.async.commit_group;\n" ::: "memory")
#define CP_WAIT(n)  asm volatile("cp.async.wait_group %0;\n" :: "n"(n) : "memory")

#define MMA_TF32(d, a, b) \
    asm volatile("mma.sync.aligned.m16n8k8.row.col.f32.tf32.tf32.f32 " \
                 "{%0,%1,%2,%3}, {%4,%5,%6,%7}, {%8,%9}, {%0,%1,%2,%3};" \
                 : "+f"(d[0]), "+f"(d[1]), "+f"(d[2]), "+f"(d[3]) \
                 : "r"(a[0]), "r"(a[1]), "r"(a[2]), "r"(a[3]), "r"(b[0]), "r"(b[1]))

// ---------------- tf32 rounding pass -----------------------------------------
__global__ void round_tf32_kernel(const float* __restrict__ in, float* __restrict__ out, int n4) {
    int i = blockIdx.x * blockDim.x + threadIdx.x;
    if (i >= n4) return;
    float4 v = ((const float4*)in)[i];
    v.x = to_tf32(v.x); v.y = to_tf32(v.y);
    v.z = to_tf32(v.z); v.w = to_tf32(v.w);
    ((float4*)out)[i] = v;
}

// ---------------- tf32 tensor-core GEMM: C[M,N] = A[M,K] * B[N,K]^T ----------
#define TBM 128
#define TBN 128
#define TBK 32
#define TSTR 36
#define GEMM_SMEM_BYTES (2 * (TBM * TSTR + TBN * TSTR) * 4)   // 73728

__global__ void __launch_bounds__(256, 2) gemm_tf32(const float* __restrict__ A,
                                                    const float* __restrict__ Bm,
                                                    float* __restrict__ Cm,
                                                    int M, int N, int K) {
    extern __shared__ float sm[];
    float* As = sm;
    float* Bs = sm + 2 * TBM * TSTR;

    const int tid = threadIdx.x;
    const int wid = tid >> 5;
    const int lane = tid & 31;
    const int warp_m = wid >> 2;
    const int warp_n = wid & 3;
    const int g = lane >> 2;
    const int t = lane & 3;

    const float* Ag = A + (size_t)blockIdx.y * TBM * K;
    const float* Bg = Bm + (size_t)blockIdx.x * TBN * K;

    float c[4][4][4];
#pragma unroll
    for (int mt = 0; mt < 4; mt++)
#pragma unroll
        for (int nt = 0; nt < 4; nt++)
#pragma unroll
            for (int r = 0; r < 4; r++) c[mt][nt][r] = 0.f;

    auto load_tile = [&](int it, int buf) {
        int k0 = it * TBK;
        float* as = As + buf * TBM * TSTR;
        float* bs = Bs + buf * TBN * TSTR;
#pragma unroll
        for (int i = 0; i < 4; i++) {
            int v = tid + i * 256;
            int r = v >> 3;
            int c4 = (v & 7) * 4;
            cp_async16(as + r * TSTR + c4, Ag + (size_t)r * K + k0 + c4);
            cp_async16(bs + r * TSTR + c4, Bg + (size_t)r * K + k0 + c4);
        }
    };

    const int NIT = K / TBK;
    load_tile(0, 0);
    CP_COMMIT();

    for (int it = 0; it < NIT; ++it) {
        int cur = it & 1;
        if (it + 1 < NIT) {
            load_tile(it + 1, cur ^ 1);
            CP_COMMIT();
            CP_WAIT(1);
        } else {
            CP_WAIT(0);
        }
        __syncthreads();

        const uint32_t* as = (const uint32_t*)(As + cur * TBM * TSTR);
        const uint32_t* bs = (const uint32_t*)(Bs + cur * TBN * TSTR);

#pragma unroll
        for (int kk = 0; kk < TBK; kk += 8) {
            uint32_t af[4][4], bf[4][2];
#pragma unroll
            for (int mt = 0; mt < 4; mt++) {
                int row = warp_m * 64 + mt * 16 + g;
                af[mt][0] = as[row * TSTR + kk + t];
                af[mt][1] = as[(row + 8) * TSTR + kk + t];
                af[mt][2] = as[row * TSTR + kk + t + 4];
                af[mt][3] = as[(row + 8) * TSTR + kk + t + 4];
            }
#pragma unroll
            for (int nt = 0; nt < 4; nt++) {
                int col = warp_n * 32 + nt * 8 + g;
                bf[nt][0] = bs[col * TSTR + kk + t];
                bf[nt][1] = bs[col * TSTR + kk + t + 4];
            }
#pragma unroll
            for (int mt = 0; mt < 4; mt++)
#pragma unroll
                for (int nt = 0; nt < 4; nt++)
                    MMA_TF32(c[mt][nt], af[mt], bf[nt]);
        }
        __syncthreads();
    }

    const int row_base = blockIdx.y * TBM + warp_m * 64;
    const int col_base = blockIdx.x * TBN + warp_n * 32;
#pragma unroll
    for (int mt = 0; mt < 4; mt++) {
#pragma unroll
        for (int nt = 0; nt < 4; nt++) {
            int row = row_base + mt * 16 + g;
            int col = col_base + nt * 8 + 2 * t;
            *(float2*)(Cm + (size_t)row * N + col)       = make_float2(c[mt][nt][0], c[mt][nt][1]);
            *(float2*)(Cm + (size_t)(row + 8) * N + col) = make_float2(c[mt][nt][2], c[mt][nt][3]);
        }
    }
}

// ---------------- RoPE on fused qkv (in place; outputs tf32-rounded) ---------
__global__ void rope_kernel(float* __restrict__ qkv, int col_off, int nheads, int total_pairs) {
    int idx = blockIdx.x * blockDim.x + threadIdx.x;
    if (idx >= total_pairs) return;
    int d   = idx & 63;
    int tmp = idx >> 6;
    int h   = tmp % nheads;
    int bt  = tmp / nheads;
    int t   = bt & (T_ - 1);

    float* base = qkv + (size_t)bt * QKVN + col_off + h * HD_;
    float x1 = base[d];
    float x2 = base[d + 64];

    int i1 = d >> 1;
    const float L2C = 0.20762050593046f; // log2(10000)/64
    float inv1 = exp2f(-(float)i1 * L2C);
    float inv2 = exp2f(-(float)(i1 + 32) * L2C);
    float a1 = (float)t * inv1;
    float a2 = (float)t * inv2;
    float s1, c1, s2, c2;
    sincosf(a1, &s1, &c1);
    sincosf(a2, &s2, &c2);

    base[d]      = to_tf32(x1 * c1 - x2 * s1);
    base[d + 64] = to_tf32(x2 * c2 + x1 * s2);
}

// ---------------- V transpose: qkv V cols -> (b,kvh,hd,t), tf32-rounded ------
__global__ void vtrans_kernel(const float* __restrict__ qkv, float* __restrict__ Vt) {
    __shared__ float tile[32][33];
    const int z = blockIdx.z;
    const int b = z / NKV_;
    const int kvh = z % NKV_;
    const int t0 = blockIdx.x * 32;
    const int h0 = blockIdx.y * 32;

#pragma unroll
    for (int i = 0; i < 4; i++) {
        int tt = t0 + threadIdx.y + i * 8;
        tile[threadIdx.y + i * 8][threadIdx.x] =
            qkv[(size_t)(b * T_ + tt) * QKVN + C_ + KVD_ + kvh * HD_ + h0 + threadIdx.x];
    }
    __syncthreads();
#pragma unroll
    for (int i = 0; i < 4; i++) {
        int hd = h0 + threadIdx.y + i * 8;
        int tt = t0 + threadIdx.x;
        Vt[((size_t)(b * NKV_ + kvh) * HD_ + hd) * T_ + tt] =
            to_tf32(tile[threadIdx.x][threadIdx.y + i * 8]);
    }
}

// ---------------- Flash attention (tf32 tensor cores, 128x64 tiles) ----------
#define ABM 128
#define ABN 64
#define AQST 132          // Q/K tile row stride
#define AVST 68           // Vt tile row stride
#define ASST 68           // S/P tile row stride

// floats: Q 128*132 + K 2*64*132 + Vt 128*68 + S 128*68 + stats 3*128
#define ATT_SMEM_FLOATS (ABM*AQST + 2*ABN*AQST + HD_*AVST + ABM*ASST + 3*ABM)
#define ATT_SMEM_BYTES  (ATT_SMEM_FLOATS * 4)   // 206336

__global__ void __launch_bounds__(256, 1) attn_kernel(const float* __restrict__ QKV,
                                                      const float* __restrict__ Vt,
                                                      float* __restrict__ O) {
    const int qt  = (int)gridDim.x - 1 - (int)blockIdx.x; // big tiles first
    const int h   = blockIdx.y;
    const int b   = blockIdx.z;
    const int kvh = h >> 1;

    extern __shared__ float sm[];
    float* Qs  = sm;                            // [128][132]
    float* Ks  = Qs + ABM * AQST;               // [2][64][132]
    float* Vs  = Ks + 2 * ABN * AQST;           // [128][68]
    float* Ss  = Vs + HD_ * AVST;               // [128][68]
    float* Ms  = Ss + ABM * ASST;
    float* Ls  = Ms + ABM;
    float* Al  = Ls + ABM;

    const int tid  = threadIdx.x;
    const int wid  = tid >> 5;
    const int lane = tid & 31;
    const int warp_m = wid & 3;                 // 0..3 -> 32-row band
    const int warp_n = wid >> 2;                // 0..1
    const int g = lane >> 2;                    // 0..7
    const int t = lane & 3;                     // 0..3
    const int rband = warp_m * 32;
    const int scol0 = warp_n * 32;              // S cols
    const int ocol0 = warp_n * 64;              // O cols (hd)

    const int q0 = qt * ABM;
    const int jtmax = 2 * qt + 1;
    const float* vtb = Vt + (size_t)(b * NKV_ + kvh) * HD_ * T_;
    const float* qb  = QKV + (size_t)(b * T_ + q0) * QKVN + h * HD_;
    const float* kb  = QKV + (size_t)(b * T_) * QKVN + C_ + kvh * HD_;

    // preload Q tile (plain loads, once)
    for (int l = tid; l < ABM * 32; l += 256) {
        int r = l >> 5;
        int c = (l & 31) * 4;
        *(float4*)(Qs + r * AQST + c) = *(const float4*)(qb + (size_t)r * QKVN + c);
    }
    if (tid < ABM) { Ms[tid] = -1e30f; Ls[tid] = 0.f; }

    auto load_k = [&](int jt, int buf) {
        const int j0 = jt * ABN;
        float* ks = Ks + buf * ABN * AQST;
#pragma unroll
        for (int i = 0; i < 8; i++) {
            int v = i * 256 + tid;
            int r = v >> 5;                 // 0..63
            int c4 = (v & 31) * 4;          // 0..124
            cp_async16(ks + r * AQST + c4, kb + (size_t)(j0 + r) * QKVN + c4);
        }
    };
    auto load_v = [&](int jt) {
        const int j0 = jt * ABN;
#pragma unroll
        for (int i = 0; i < 8; i++) {
            int v = i * 256 + tid;
            int r = v >> 4;                 // 0..127 (hd)
            int c4 = (v & 15) * 4;          // 0..60 (seq)
            cp_async16(Vs + r * AVST + c4, vtb + (size_t)r * T_ + j0 + c4);
        }
    };

    float o[2][8][4];
#pragma unroll
    for (int mt = 0; mt < 2; mt++)
#pragma unroll
        for (int nt = 0; nt < 8; nt++)
#pragma unroll
            for (int r = 0; r < 4; r++) o[mt][nt][r] = 0.f;

    load_k(0, 0);
    CP_COMMIT();
    __syncthreads();      // Q tile + stats visible; also orders first V write

    const float scale = 0.08838834764831845f; // 1/sqrt(128)

    for (int jt = 0; jt <= jtmax; jt++) {
        const int cur = jt & 1;
        // V(jt) into single buffer (safe: all warps passed end-of-prev-iter sync)
        load_v(jt);
        CP_COMMIT();
        if (jt < jtmax) {
            load_k(jt + 1, cur ^ 1);
            CP_COMMIT();
            CP_WAIT(2);   // K(jt) complete; V(jt), K(jt+1) in flight
        } else {
            CP_WAIT(1);   // K(jt) complete; V(jt) in flight
        }
        __syncthreads();

        // ---- S = Q K^T ----
        const uint32_t* qs = (const uint32_t*)Qs;
        const uint32_t* ks = (const uint32_t*)(Ks + cur * ABN * AQST);
        float s[2][4][4];
#pragma unroll
        for (int mt = 0; mt < 2; mt++)
#pragma unroll
            for (int nt = 0; nt < 4; nt++)
#pragma unroll
                for (int r = 0; r < 4; r++) s[mt][nt][r] = 0.f;

#pragma unroll
        for (int kk = 0; kk < HD_; kk += 8) {
            uint32_t af[2][4], bf[4][2];
#pragma unroll
            for (int mt = 0; mt < 2; mt++) {
                int r0 = rband + mt * 16;
                af[mt][0] = qs[(r0 + g) * AQST + kk + t];
                af[mt][1] = qs[(r0 + 8 + g) * AQST + kk + t];
                af[mt][2] = qs[(r0 + g) * AQST + kk + t + 4];
                af[mt][3] = qs[(r0 + 8 + g) * AQST + kk + t + 4];
            }
#pragma unroll
            for (int nt = 0; nt < 4; nt++) {
                int col = scol0 + nt * 8 + g;
                bf[nt][0] = ks[col * AQST + kk + t];
                bf[nt][1] = ks[col * AQST + kk + t + 4];
            }
#pragma unroll
            for (int mt = 0; mt < 2; mt++)
#pragma unroll
                for (int nt = 0; nt < 4; nt++)
                    MMA_TF32(s[mt][nt], af[mt], bf[nt]);
        }

        // ---- scale + causal mask + store ----
        const bool diag = (jt >= 2 * qt);
#pragma unroll
        for (int mt = 0; mt < 2; mt++) {
#pragma unroll
            for (int nt = 0; nt < 4; nt++) {
                int c0 = scol0 + nt * 8 + 2 * t;
                int rlo = rband + mt * 16 + g, rhi = rlo + 8;
                float v0 = s[mt][nt][0] * scale, v1 = s[mt][nt][1] * scale;
                float v2 = s[mt][nt][2] * scale, v3 = s[mt][nt][3] * scale;
                if (diag) {
                    int gc0 = jt * ABN + c0;
                    if (gc0     > q0 + rlo) v0 = -1e30f;
                    if (gc0 + 1 > q0 + rlo) v1 = -1e30f;
                    if (gc0     > q0 + rhi) v2 = -1e30f;
                    if (gc0 + 1 > q0 + rhi) v3 = -1e30f;
                }
                *(float2*)(Ss + rlo * ASST + c0) = make_float2(v0, v1);
                *(float2*)(Ss + rhi * ASST + c0) = make_float2(v2, v3);
            }
        }
        __syncthreads();

        // ---- online softmax: 2 threads per row ----
        {
            int row = tid >> 1;
            int q2 = tid & 1;
            float mprev = Ms[row];
            float mx = -1e30f;
#pragma unroll
            for (int i = 0; i < 32; i++)
                mx = fmaxf(mx, Ss[row * ASST + q2 + 2 * i]);
            mx = fmaxf(mx, __shfl_xor_sync(0xffffffffu, mx, 1));
            mx = fmaxf(mx, mprev);
            float sum = 0.f;
#pragma unroll
            for (int i = 0; i < 32; i++) {
                float p = to_tf32(__expf(Ss[row * ASST + q2 + 2 * i] - mx));
                Ss[row * ASST + q2 + 2 * i] = p;
                sum += p;
            }
            sum += __shfl_xor_sync(0xffffffffu, sum, 1);
            if (q2 == 0) {
                float alpha = __expf(mprev - mx);
                Ms[row] = mx;
                Ls[row] = Ls[row] * alpha + sum;
                Al[row] = alpha;
            }
        }
        // V(jt) must be complete before PV
        if (jt < jtmax) { CP_WAIT(1); } else { CP_WAIT(0); }
        __syncthreads();

        // ---- O = alpha*O + P @ V ----
        {
            const uint32_t* ss = (const uint32_t*)Ss;
            const uint32_t* vs = (const uint32_t*)Vs;
#pragma unroll
            for (int mt = 0; mt < 2; mt++) {
                float al_lo = Al[rband + mt * 16 + g];
                float al_hi = Al[rband + mt * 16 + 8 + g];
#pragma unroll
                for (int nt = 0; nt < 8; nt++) {
                    o[mt][nt][0] *= al_lo; o[mt][nt][1] *= al_lo;
                    o[mt][nt][2] *= al_hi; o[mt][nt][3] *= al_hi;
                }
            }
#pragma unroll
            for (int kk = 0; kk < ABN; kk += 8) {
                uint32_t af[2][4], bf[8][2];
#pragma unroll
                for (int mt = 0; mt < 2; mt++) {
                    int r0 = rband + mt * 16;
                    af[mt][0] = ss[(r0 + g) * ASST + kk + t];
                    af[mt][1] = ss[(r0 + 8 + g) * ASST + kk + t];
                    af[mt][2] = ss[(r0 + g) * ASST + kk + t + 4];
                    af[mt][3] = ss[(r0 + 8 + g) * ASST + kk + t + 4];
                }
#pragma unroll
                for (int nt = 0; nt < 8; nt++) {
                    int n = ocol0 + nt * 8 + g;
                    bf[nt][0] = vs[n * AVST + kk + t];
                    bf[nt][1] = vs[n * AVST + kk + t + 4];
                }
#pragma unroll
                for (int mt = 0; mt < 2; mt++)
#pragma unroll
                    for (int nt = 0; nt < 8; nt++)
                        MMA_TF32(o[mt][nt], af[mt], bf[nt]);
            }
        }
        __syncthreads();   // protect V/Ss rewrite next iter
    }

    // ---- epilogue ----
#pragma unroll
    for (int mt = 0; mt < 2; mt++) {
        int rlo = rband + mt * 16 + g, rhi = rlo + 8;
        float inv_lo = 1.f / Ls[rlo];
        float inv_hi = 1.f / Ls[rhi];
        float* dlo = O + ((size_t)(b * T_ + q0 + rlo) * NH_ + h) * HD_;
        float* dhi = O + ((size_t)(b * T_ + q0 + rhi) * NH_ + h) * HD_;
#pragma unroll
        for (int nt = 0; nt < 8; nt++) {
            int col = ocol0 + nt * 8 + 2 * t;
            *(float2*)(dlo + col) = make_float2(to_tf32(o[mt][nt][0] * inv_lo),
                                                to_tf32(o[mt][nt][1] * inv_lo));
            *(float2*)(dhi + col) = make_float2(to_tf32(o[mt][nt][2] * inv_hi),
                                                to_tf32(o[mt][nt][3] * inv_hi));
        }
    }
}

// ---------------- launch ------------------------------------------------------
extern "C" void kernel_launch(void* const* d_in, const int* in_sizes, int n_in,
                              void* d_out, int out_size) {
    const float* x  = (const float*)d_in[0];
    const float* Wq = (const float*)d_in[1];
    const float* Wk = (const float*)d_in[2];
    const float* Wv = (const float*)d_in[3];
    const float* Wo = (const float*)d_in[4];
    float* y = (float*)d_out;

    float *qkv, *vt, *o, *xr, *wqkv, *wor;
    cudaGetSymbolAddress((void**)&qkv, g_qkv);
    cudaGetSymbolAddress((void**)&vt,  g_vt);
    cudaGetSymbolAddress((void**)&o,   g_o);
    cudaGetSymbolAddress((void**)&xr,  g_xr);
    cudaGetSymbolAddress((void**)&wqkv, g_wqkv);
    cudaGetSymbolAddress((void**)&wor, g_wor);

    cudaFuncSetAttribute(attn_kernel, cudaFuncAttributeMaxDynamicSharedMemorySize,
                         ATT_SMEM_BYTES);
    cudaFuncSetAttribute(gemm_tf32, cudaFuncAttributeMaxDynamicSharedMemorySize,
                         GEMM_SMEM_BYTES);

    // tf32 pre-rounding; Wq|Wk|Wv concatenated into one weight matrix
    {
        int n4x = M_ * C_ / 4;
        int n4q = C_ * C_ / 4;
        int n4k = KVD_ * C_ / 4;
        round_tf32_kernel<<<(n4x + 255) / 256, 256>>>(x,  xr,  n4x);
        round_tf32_kernel<<<(n4q + 255) / 256, 256>>>(Wq, wqkv, n4q);
        round_tf32_kernel<<<(n4k + 255) / 256, 256>>>(Wk, wqkv + (size_t)C_ * C_, n4k);
        round_tf32_kernel<<<(n4k + 255) / 256, 256>>>(Wv, wqkv + (size_t)(C_ + KVD_) * C_, n4k);
        round_tf32_kernel<<<(n4q + 255) / 256, 256>>>(Wo, wor, n4q);
    }

    // fused QKV projection: [8192 x 4096] = xr @ Wqkv^T
    gemm_tf32<<<dim3(QKVN / TBN, M_ / TBM), 256, GEMM_SMEM_BYTES>>>(xr, wqkv, qkv, M_, QKVN, C_);

    // RoPE on q (cols 0..2047) and k (cols 2048..3071), tf32-rounded outputs
    {
        int qpairs = M_ * NH_ * 64;
        int kpairs = M_ * NKV_ * 64;
        rope_kernel<<<(qpairs + 255) / 256, 256>>>(qkv, 0,  NH_,  qpairs);
        rope_kernel<<<(kpairs + 255) / 256, 256>>>(qkv, C_, NKV_, kpairs);
    }

    // V transpose from qkv cols 3072..4095 -> (b,kvh,hd,t), tf32-rounded
    vtrans_kernel<<<dim3(T_ / 32, HD_ / 32, B_ * NKV_), dim3(32, 8)>>>(qkv, vt);

    // attention (tensor cores, 128-row Q tiles)
    attn_kernel<<<dim3(T_ / ABM, NH_, B_), 256, ATT_SMEM_BYTES>>>(qkv, vt, o);

    // output projection
    gemm_tf32<<<dim3(C_ / TBN, M_ / TBM), 256, GEMM_SMEM_BYTES>>>(o, wor, y, M_, C_, C_);
}

// round 9
// speedup vs baseline: 7.8357x; 1.0850x over previous
#include <cuda_runtime.h>
#include <cuda_bf16.h>
#include <math.h>
#include <stdint.h>

// Problem constants
#define B_    4
#define T_    2048
#define C_    2048
#define NH_   16
#define NKV_  8
#define HD_   128
#define M_    (B_*T_)          // 8192
#define KVD_  (NKV_*HD_)       // 1024
#define QKVN  (C_ + 2*KVD_)    // 4096 fused projection width

// ---------------- scratch ----------------------------------------------------
__device__ float g_qkv[(size_t)M_ * QKVN];   // fused QKV output
__device__ float g_vt[(size_t)B_ * NKV_ * HD_ * T_]; // V transposed, tf32
__device__ float g_o[(size_t)M_ * C_];       // attention out (tf32-rounded)
__device__ float g_xr[(size_t)M_ * C_];      // x rounded to tf32
__device__ float g_wqkv[(size_t)QKVN * C_];  // concat rounded Wq|Wk|Wv
__device__ float g_wor[(size_t)C_ * C_];

// ---------------- helpers ----------------------------------------------------
__device__ __forceinline__ float to_tf32(float x) {
    uint32_t u;
    asm("cvt.rna.tf32.f32 %0, %1;" : "=r"(u) : "f"(x));
    return __uint_as_float(u);
}

__device__ __forceinline__ void cp_async16(void* smem, const void* gmem) {
    uint32_t sa = (uint32_t)__cvta_generic_to_shared(smem);
    asm volatile("cp.async.cg.shared.global [%0], [%1], 16;\n" :: "r"(sa), "l"(gmem));
}
#define CP_COMMIT() asm volatile("cp.async.commit_group;\n" ::: "memory")
#define CP_WAIT(n)  asm volatile("cp.async.wait_group %0;\n" :: "n"(n) : "memory")

#define MMA_TF32(d, a, b) \
    asm volatile("mma.sync.aligned.m16n8k8.row.col.f32.tf32.tf32.f32 " \
                 "{%0,%1,%2,%3}, {%4,%5,%6,%7}, {%8,%9}, {%0,%1,%2,%3};" \
                 : "+f"(d[0]), "+f"(d[1]), "+f"(d[2]), "+f"(d[3]) \
                 : "r"(a[0]), "r"(a[1]), "r"(a[2]), "r"(a[3]), "r"(b[0]), "r"(b[1]))

// ldmatrix x4: one call = 4 8x4-tf32 tiles; per-thread address = row pointer.
__device__ __forceinline__ void ldsm4(uint32_t* r, const float* p) {
    uint32_t a = (uint32_t)__cvta_generic_to_shared(p);
    asm volatile("ldmatrix.sync.aligned.m8n8.x4.shared.b16 {%0,%1,%2,%3}, [%4];"
                 : "=r"(r[0]), "=r"(r[1]), "=r"(r[2]), "=r"(r[3]) : "r"(a));
}

// ---------------- fused tf32 rounding pass (one launch, 5 regions) ----------
__global__ void round_all_kernel(const float* __restrict__ x,  const float* __restrict__ Wq,
                                 const float* __restrict__ Wk, const float* __restrict__ Wv,
                                 const float* __restrict__ Wo,
                                 float* __restrict__ xr, float* __restrict__ wqkv,
                                 float* __restrict__ wor) {
    size_t i = (size_t)blockIdx.x * blockDim.x + threadIdx.x;
    const size_t NX = (size_t)M_ * C_ / 4;
    const size_t NQ = (size_t)C_ * C_ / 4;
    const size_t NK = (size_t)KVD_ * C_ / 4;
    const float4* src; float4* dst; size_t off;
    if (i < NX)                    { src = (const float4*)x;  dst = (float4*)xr;   off = i; }
    else if (i < NX + NQ)          { src = (const float4*)Wq; dst = (float4*)wqkv; off = i - NX; }
    else if (i < NX + NQ + NK)     { src = (const float4*)Wk; dst = (float4*)(wqkv + (size_t)C_ * C_); off = i - NX - NQ; }
    else if (i < NX + NQ + 2*NK)   { src = (const float4*)Wv; dst = (float4*)(wqkv + (size_t)(C_ + KVD_) * C_); off = i - NX - NQ - NK; }
    else if (i < NX + 2*NQ + 2*NK) { src = (const float4*)Wo; dst = (float4*)wor;  off = i - NX - NQ - 2*NK; }
    else return;
    float4 v = src[off];
    v.x = to_tf32(v.x); v.y = to_tf32(v.y);
    v.z = to_tf32(v.z); v.w = to_tf32(v.w);
    dst[off] = v;
}
#define ROUND_TOTAL4 ((size_t)M_*C_/4 + 2*((size_t)C_*C_/4) + 2*((size_t)KVD_*C_/4))

// ---------------- tf32 tensor-core GEMM: C[M,N] = A[M,K] * B[N,K]^T ----------
#define TBM 128
#define TBN 128
#define TBK 32
#define TSTR 36
#define GEMM_SMEM_BYTES (2 * (TBM * TSTR + TBN * TSTR) * 4)   // 73728

__global__ void __launch_bounds__(256, 2) gemm_tf32(const float* __restrict__ A,
                                                    const float* __restrict__ Bm,
                                                    float* __restrict__ Cm,
                                                    int M, int N, int K) {
    extern __shared__ float sm[];
    float* As = sm;
    float* Bs = sm + 2 * TBM * TSTR;

    const int tid = threadIdx.x;
    const int wid = tid >> 5;
    const int lane = tid & 31;
    const int warp_m = wid >> 2;
    const int warp_n = wid & 3;
    const int g = lane >> 2;
    const int t = lane & 3;

    // ldmatrix per-thread row/col offsets
    const int rowA  = lane & 15;            // + warp_m*64 + mt*16
    const int koffA = (lane >> 4) * 4;
    const int rowB  = (lane & 7) + ((lane >> 4) << 3);  // + warp_n*32 + np*16
    const int koffB = ((lane >> 3) & 1) * 4;

    const float* Ag = A + (size_t)blockIdx.y * TBM * K;
    const float* Bg = Bm + (size_t)blockIdx.x * TBN * K;

    float c[4][4][4];
#pragma unroll
    for (int mt = 0; mt < 4; mt++)
#pragma unroll
        for (int nt = 0; nt < 4; nt++)
#pragma unroll
            for (int r = 0; r < 4; r++) c[mt][nt][r] = 0.f;

    auto load_tile = [&](int it, int buf) {
        int k0 = it * TBK;
        float* as = As + buf * TBM * TSTR;
        float* bs = Bs + buf * TBN * TSTR;
#pragma unroll
        for (int i = 0; i < 4; i++) {
            int v = tid + i * 256;
            int r = v >> 3;
            int c4 = (v & 7) * 4;
            cp_async16(as + r * TSTR + c4, Ag + (size_t)r * K + k0 + c4);
            cp_async16(bs + r * TSTR + c4, Bg + (size_t)r * K + k0 + c4);
        }
    };

    const int NIT = K / TBK;
    load_tile(0, 0);
    CP_COMMIT();

    for (int it = 0; it < NIT; ++it) {
        int cur = it & 1;
        if (it + 1 < NIT) {
            load_tile(it + 1, cur ^ 1);
            CP_COMMIT();
            CP_WAIT(1);
        } else {
            CP_WAIT(0);
        }
        __syncthreads();

        const float* as = As + cur * TBM * TSTR;
        const float* bs = Bs + cur * TBN * TSTR;

#pragma unroll
        for (int kk = 0; kk < TBK; kk += 8) {
            uint32_t af[4][4], bf4[2][4];
#pragma unroll
            for (int mt = 0; mt < 4; mt++)
                ldsm4(af[mt], as + (warp_m * 64 + mt * 16 + rowA) * TSTR + kk + koffA);
#pragma unroll
            for (int np = 0; np < 2; np++)
                ldsm4(bf4[np], bs + (warp_n * 32 + np * 16 + rowB) * TSTR + kk + koffB);
#pragma unroll
            for (int mt = 0; mt < 4; mt++)
#pragma unroll
                for (int nt = 0; nt < 4; nt++)
                    MMA_TF32(c[mt][nt], af[mt], (&bf4[nt >> 1][(nt & 1) * 2]));
        }
        __syncthreads();
    }

    const int row_base = blockIdx.y * TBM + warp_m * 64;
    const int col_base = blockIdx.x * TBN + warp_n * 32;
#pragma unroll
    for (int mt = 0; mt < 4; mt++) {
#pragma unroll
        for (int nt = 0; nt < 4; nt++) {
            int row = row_base + mt * 16 + g;
            int col = col_base + nt * 8 + 2 * t;
            *(float2*)(Cm + (size_t)row * N + col)       = make_float2(c[mt][nt][0], c[mt][nt][1]);
            *(float2*)(Cm + (size_t)(row + 8) * N + col) = make_float2(c[mt][nt][2], c[mt][nt][3]);
        }
    }
}

// ---------------- RoPE on fused qkv (in place; outputs tf32-rounded) ---------
__global__ void rope_kernel(float* __restrict__ qkv, int col_off, int nheads, int total_pairs) {
    int idx = blockIdx.x * blockDim.x + threadIdx.x;
    if (idx >= total_pairs) return;
    int d   = idx & 63;
    int tmp = idx >> 6;
    int h   = tmp % nheads;
    int bt  = tmp / nheads;
    int t   = bt & (T_ - 1);

    float* base = qkv + (size_t)bt * QKVN + col_off + h * HD_;
    float x1 = base[d];
    float x2 = base[d + 64];

    int i1 = d >> 1;
    const float L2C = 0.20762050593046f; // log2(10000)/64
    float inv1 = exp2f(-(float)i1 * L2C);
    float inv2 = exp2f(-(float)(i1 + 32) * L2C);
    float a1 = (float)t * inv1;
    float a2 = (float)t * inv2;
    float s1, c1, s2, c2;
    sincosf(a1, &s1, &c1);
    sincosf(a2, &s2, &c2);

    base[d]      = to_tf32(x1 * c1 - x2 * s1);
    base[d + 64] = to_tf32(x2 * c2 + x1 * s2);
}

// ---------------- V transpose: qkv V cols -> (b,kvh,hd,t), tf32-rounded ------
__global__ void vtrans_kernel(const float* __restrict__ qkv, float* __restrict__ Vt) {
    __shared__ float tile[32][33];
    const int z = blockIdx.z;
    const int b = z / NKV_;
    const int kvh = z % NKV_;
    const int t0 = blockIdx.x * 32;
    const int h0 = blockIdx.y * 32;

#pragma unroll
    for (int i = 0; i < 4; i++) {
        int tt = t0 + threadIdx.y + i * 8;
        tile[threadIdx.y + i * 8][threadIdx.x] =
            qkv[(size_t)(b * T_ + tt) * QKVN + C_ + KVD_ + kvh * HD_ + h0 + threadIdx.x];
    }
    __syncthreads();
#pragma unroll
    for (int i = 0; i < 4; i++) {
        int hd = h0 + threadIdx.y + i * 8;
        int tt = t0 + threadIdx.x;
        Vt[((size_t)(b * NKV_ + kvh) * HD_ + hd) * T_ + tt] =
            to_tf32(tile[threadIdx.x][threadIdx.y + i * 8]);
    }
}

// ---------------- Flash attention (tf32 tensor cores, 128x64 tiles) ----------
#define ABM 128
#define ABN 64
#define AQST 132          // Q/K tile row stride
#define AVST 68           // Vt tile row stride
#define ASST 68           // S/P tile row stride

#define ATT_SMEM_FLOATS (ABM*AQST + 2*ABN*AQST + HD_*AVST + ABM*ASST + 3*ABM)
#define ATT_SMEM_BYTES  (ATT_SMEM_FLOATS * 4)   // 206336

__global__ void __launch_bounds__(256, 1) attn_kernel(const float* __restrict__ QKV,
                                                      const float* __restrict__ Vt,
                                                      float* __restrict__ O) {
    const int qt  = (int)gridDim.x - 1 - (int)blockIdx.x; // big tiles first
    const int h   = blockIdx.y;
    const int b   = blockIdx.z;
    const int kvh = h >> 1;

    extern __shared__ float sm[];
    float* Qs  = sm;                            // [128][132]
    float* Ks  = Qs + ABM * AQST;               // [2][64][132]
    float* Vs  = Ks + 2 * ABN * AQST;           // [128][68]
    float* Ss  = Vs + HD_ * AVST;               // [128][68]
    float* Ms  = Ss + ABM * ASST;
    float* Ls  = Ms + ABM;
    float* Al  = Ls + ABM;

    const int tid  = threadIdx.x;
    const int wid  = tid >> 5;
    const int lane = tid & 31;
    const int warp_m = wid & 3;                 // 0..3 -> 32-row band
    const int warp_n = wid >> 2;                // 0..1
    const int g = lane >> 2;
    const int t = lane & 3;
    const int rband = warp_m * 32;
    const int scol0 = warp_n * 32;              // S cols
    const int ocol0 = warp_n * 64;              // O cols (hd)

    // ldmatrix per-thread offsets
    const int rowA  = lane & 15;
    const int koffA = (lane >> 4) * 4;
    const int rowB  = (lane & 7) + ((lane >> 4) << 3);
    const int koffB = ((lane >> 3) & 1) * 4;

    const int q0 = qt * ABM;
    const int jtmax = 2 * qt + 1;
    const float* vtb = Vt + (size_t)(b * NKV_ + kvh) * HD_ * T_;
    const float* qb  = QKV + (size_t)(b * T_ + q0) * QKVN + h * HD_;
    const float* kb  = QKV + (size_t)(b * T_) * QKVN + C_ + kvh * HD_;

    // preload Q tile
    for (int l = tid; l < ABM * 32; l += 256) {
        int r = l >> 5;
        int c = (l & 31) * 4;
        *(float4*)(Qs + r * AQST + c) = *(const float4*)(qb + (size_t)r * QKVN + c);
    }
    if (tid < ABM) { Ms[tid] = -1e30f; Ls[tid] = 0.f; }

    auto load_k = [&](int jt, int buf) {
        const int j0 = jt * ABN;
        float* ks = Ks + buf * ABN * AQST;
#pragma unroll
        for (int i = 0; i < 8; i++) {
            int v = i * 256 + tid;
            int r = v >> 5;
            int c4 = (v & 31) * 4;
            cp_async16(ks + r * AQST + c4, kb + (size_t)(j0 + r) * QKVN + c4);
        }
    };
    auto load_v = [&](int jt) {
        const int j0 = jt * ABN;
#pragma unroll
        for (int i = 0; i < 8; i++) {
            int v = i * 256 + tid;
            int r = v >> 4;
            int c4 = (v & 15) * 4;
            cp_async16(Vs + r * AVST + c4, vtb + (size_t)r * T_ + j0 + c4);
        }
    };

    float o[2][8][4];
#pragma unroll
    for (int mt = 0; mt < 2; mt++)
#pragma unroll
        for (int nt = 0; nt < 8; nt++)
#pragma unroll
            for (int r = 0; r < 4; r++) o[mt][nt][r] = 0.f;

    load_k(0, 0);
    CP_COMMIT();
    __syncthreads();

    const float scale = 0.08838834764831845f; // 1/sqrt(128)

    for (int jt = 0; jt <= jtmax; jt++) {
        const int cur = jt & 1;
        load_v(jt);
        CP_COMMIT();
        if (jt < jtmax) {
            load_k(jt + 1, cur ^ 1);
            CP_COMMIT();
            CP_WAIT(2);
        } else {
            CP_WAIT(1);
        }
        __syncthreads();

        // ---- S = Q K^T ----
        const float* ksf = Ks + cur * ABN * AQST;
        float s[2][4][4];
#pragma unroll
        for (int mt = 0; mt < 2; mt++)
#pragma unroll
            for (int nt = 0; nt < 4; nt++)
#pragma unroll
                for (int r = 0; r < 4; r++) s[mt][nt][r] = 0.f;

#pragma unroll
        for (int kk = 0; kk < HD_; kk += 8) {
            uint32_t af[2][4], bf4[2][4];
#pragma unroll
            for (int mt = 0; mt < 2; mt++)
                ldsm4(af[mt], Qs + (rband + mt * 16 + rowA) * AQST + kk + koffA);
#pragma unroll
            for (int np = 0; np < 2; np++)
                ldsm4(bf4[np], ksf + (scol0 + np * 16 + rowB) * AQST + kk + koffB);
#pragma unroll
            for (int mt = 0; mt < 2; mt++)
#pragma unroll
                for (int nt = 0; nt < 4; nt++)
                    MMA_TF32(s[mt][nt], af[mt], (&bf4[nt >> 1][(nt & 1) * 2]));
        }

        // ---- scale + causal mask + store ----
        const bool diag = (jt >= 2 * qt);
#pragma unroll
        for (int mt = 0; mt < 2; mt++) {
#pragma unroll
            for (int nt = 0; nt < 4; nt++) {
                int c0 = scol0 + nt * 8 + 2 * t;
                int rlo = rband + mt * 16 + g, rhi = rlo + 8;
                float v0 = s[mt][nt][0] * scale, v1 = s[mt][nt][1] * scale;
                float v2 = s[mt][nt][2] * scale, v3 = s[mt][nt][3] * scale;
                if (diag) {
                    int gc0 = jt * ABN + c0;
                    if (gc0     > q0 + rlo) v0 = -1e30f;
                    if (gc0 + 1 > q0 + rlo) v1 = -1e30f;
                    if (gc0     > q0 + rhi) v2 = -1e30f;
                    if (gc0 + 1 > q0 + rhi) v3 = -1e30f;
                }
                *(float2*)(Ss + rlo * ASST + c0) = make_float2(v0, v1);
                *(float2*)(Ss + rhi * ASST + c0) = make_float2(v2, v3);
            }
        }
        __syncthreads();

        // ---- online softmax: 2 threads per row ----
        {
            int row = tid >> 1;
            int q2 = tid & 1;
            float mprev = Ms[row];
            float mx = -1e30f;
#pragma unroll
            for (int i = 0; i < 32; i++)
                mx = fmaxf(mx, Ss[row * ASST + q2 + 2 * i]);
            mx = fmaxf(mx, __shfl_xor_sync(0xffffffffu, mx, 1));
            mx = fmaxf(mx, mprev);
            float sum = 0.f;
#pragma unroll
            for (int i = 0; i < 32; i++) {
                float p = to_tf32(__expf(Ss[row * ASST + q2 + 2 * i] - mx));
                Ss[row * ASST + q2 + 2 * i] = p;
                sum += p;
            }
            sum += __shfl_xor_sync(0xffffffffu, sum, 1);
            if (q2 == 0) {
                float alpha = __expf(mprev - mx);
                Ms[row] = mx;
                Ls[row] = Ls[row] * alpha + sum;
                Al[row] = alpha;
            }
        }
        if (jt < jtmax) { CP_WAIT(1); } else { CP_WAIT(0); }
        __syncthreads();

        // ---- O = alpha*O + P @ V ----
        {
#pragma unroll
            for (int mt = 0; mt < 2; mt++) {
                float al_lo = Al[rband + mt * 16 + g];
                float al_hi = Al[rband + mt * 16 + 8 + g];
#pragma unroll
                for (int nt = 0; nt < 8; nt++) {
                    o[mt][nt][0] *= al_lo; o[mt][nt][1] *= al_lo;
                    o[mt][nt][2] *= al_hi; o[mt][nt][3] *= al_hi;
                }
            }
#pragma unroll
            for (int kk = 0; kk < ABN; kk += 8) {
                uint32_t af[2][4], bf4[4][4];
#pragma unroll
                for (int mt = 0; mt < 2; mt++)
                    ldsm4(af[mt], Ss + (rband + mt * 16 + rowA) * ASST + kk + koffA);
#pragma unroll
                for (int np = 0; np < 4; np++)
                    ldsm4(bf4[np], Vs + (ocol0 + np * 16 + rowB) * AVST + kk + koffB);
#pragma unroll
                for (int mt = 0; mt < 2; mt++)
#pragma unroll
                    for (int nt = 0; nt < 8; nt++)
                        MMA_TF32(o[mt][nt], af[mt], (&bf4[nt >> 1][(nt & 1) * 2]));
            }
        }
        __syncthreads();
    }

    // ---- epilogue ----
#pragma unroll
    for (int mt = 0; mt < 2; mt++) {
        int rlo = rband + mt * 16 + g, rhi = rlo + 8;
        float inv_lo = 1.f / Ls[rlo];
        float inv_hi = 1.f / Ls[rhi];
        float* dlo = O + ((size_t)(b * T_ + q0 + rlo) * NH_ + h) * HD_;
        float* dhi = O + ((size_t)(b * T_ + q0 + rhi) * NH_ + h) * HD_;
#pragma unroll
        for (int nt = 0; nt < 8; nt++) {
            int col = ocol0 + nt * 8 + 2 * t;
            *(float2*)(dlo + col) = make_float2(to_tf32(o[mt][nt][0] * inv_lo),
                                                to_tf32(o[mt][nt][1] * inv_lo));
            *(float2*)(dhi + col) = make_float2(to_tf32(o[mt][nt][2] * inv_hi),
                                                to_tf32(o[mt][nt][3] * inv_hi));
        }
    }
}

// ---------------- launch ------------------------------------------------------
extern "C" void kernel_launch(void* const* d_in, const int* in_sizes, int n_in,
                              void* d_out, int out_size) {
    const float* x  = (const float*)d_in[0];
    const float* Wq = (const float*)d_in[1];
    const float* Wk = (const float*)d_in[2];
    const float* Wv = (const float*)d_in[3];
    const float* Wo = (const float*)d_in[4];
    float* y = (float*)d_out;

    float *qkv, *vt, *o, *xr, *wqkv, *wor;
    cudaGetSymbolAddress((void**)&qkv, g_qkv);
    cudaGetSymbolAddress((void**)&vt,  g_vt);
    cudaGetSymbolAddress((void**)&o,   g_o);
    cudaGetSymbolAddress((void**)&xr,  g_xr);
    cudaGetSymbolAddress((void**)&wqkv, g_wqkv);
    cudaGetSymbolAddress((void**)&wor, g_wor);

    cudaFuncSetAttribute(attn_kernel, cudaFuncAttributeMaxDynamicSharedMemorySize,
                         ATT_SMEM_BYTES);
    cudaFuncSetAttribute(gemm_tf32, cudaFuncAttributeMaxDynamicSharedMemorySize,
                         GEMM_SMEM_BYTES);

    // fused tf32 pre-rounding (one launch)
    {
        size_t n4 = ROUND_TOTAL4;
        round_all_kernel<<<(unsigned)((n4 + 255) / 256), 256>>>(x, Wq, Wk, Wv, Wo,
                                                                xr, wqkv, wor);
    }

    // fused QKV projection: [8192 x 4096] = xr @ Wqkv^T
    gemm_tf32<<<dim3(QKVN / TBN, M_ / TBM), 256, GEMM_SMEM_BYTES>>>(xr, wqkv, qkv, M_, QKVN, C_);

    // RoPE on q and k, tf32-rounded outputs
    {
        int qpairs = M_ * NH_ * 64;
        int kpairs = M_ * NKV_ * 64;
        rope_kernel<<<(qpairs + 255) / 256, 256>>>(qkv, 0,  NH_,  qpairs);
        rope_kernel<<<(kpairs + 255) / 256, 256>>>(qkv, C_, NKV_, kpairs);
    }

    // V transpose -> (b,kvh,hd,t), tf32-rounded
    vtrans_kernel<<<dim3(T_ / 32, HD_ / 32, B_ * NKV_), dim3(32, 8)>>>(qkv, vt);

    // attention (tensor cores, 128-row Q tiles)
    attn_kernel<<<dim3(T_ / ABM, NH_, B_), 256, ATT_SMEM_BYTES>>>(qkv, vt, o);

    // output projection
    gemm_tf32<<<dim3(C_ / TBN, M_ / TBM), 256, GEMM_SMEM_BYTES>>>(o, wor, y, M_, C_, C_);
}